// round 2
// baseline (speedup 1.0000x reference)
#include <cuda_runtime.h>
#include <stdint.h>

#define BATCH  64
#define NIN    784
#define NHID   2048
#define NOUT   10
#define NN     2058
#define NE     262144
#define TSTEPS 30
#define NBLK   148
#define NTHR   512
#define NWARP  (NBLK*NTHR/32)            // 2368
#define EPW    ((NE + NWARP - 1)/NWARP)  // 111
#define NELEM  (NN*BATCH)                // 131712
#define TPG    (NBLK*NTHR)               // 75776

// ---------------- static device state ----------------
__device__ uint8_t  d_cnt[NE*BATCH];          // 16MB countdown timers [e][b]
__device__ float    d_ring[16*NELEM];         // future current ring [slot][n*64+b]
__device__ float    d_vm[NELEM];              // membrane [n*64+b]
__device__ float    d_vexc[2][NHID*BATCH];    // double-buffered V_exc
__device__ uint32_t d_fired[2][NHID*2];       // double-buffered fired bitmasks (64b/neuron)
__device__ float    d_acc[NOUT*BATCH];        // output accumulator [o*64+b]
__device__ float    d_inp[NHID*BATCH];        // input currents [n*64+b]
__device__ uint32_t d_meta[NE];               // src | tgt<<11 | (2L)<<23
__device__ float    d_wgt[NE];
__device__ unsigned g_cnt = 0;
__device__ volatile unsigned g_gen = 0;

// ---------------- init ----------------
__global__ void init_kernel(const float* __restrict__ We, const float* __restrict__ Le,
                            const int* __restrict__ src, const int* __restrict__ tgt) {
    int g = blockIdx.x * blockDim.x + threadIdx.x;
    int st = gridDim.x * blockDim.x;
    uint32_t* c32 = (uint32_t*)d_cnt;
    for (int i = g; i < NE*BATCH/4; i += st) c32[i] = 0u;
    for (int i = g; i < 16*NELEM;   i += st) d_ring[i] = 0.f;
    for (int i = g; i < NELEM;      i += st) d_vm[i] = 0.f;
    for (int i = g; i < NOUT*BATCH; i += st) d_acc[i] = 0.f;
    for (int e = g; e < NE; e += st) {
        int d = (int)(Le[e] * 2.0f + 0.5f);   // 6..15
        d_meta[e] = (uint32_t)src[e] | ((uint32_t)tgt[e] << 11) | ((uint32_t)d << 23);
        d_wgt[e] = We[e];
    }
}

// ---------------- input currents: inp[n*64+b] = sum_k x[b][k] * W[k][n] ----------------
__global__ void gemm_kernel(const float* __restrict__ x, const float* __restrict__ W) {
    __shared__ float sx[4][NIN];
    int n  = blockIdx.x * 256 + threadIdx.x;     // blockIdx.x in [0,8)
    int b0 = blockIdx.y * 4;                     // blockIdx.y in [0,16)
    for (int i = threadIdx.x; i < 4*NIN; i += 256) {
        int bb = i / NIN, kk = i - bb * NIN;
        sx[bb][kk] = x[(b0 + bb) * NIN + kk];
    }
    __syncthreads();
    float a0 = 0.f, a1 = 0.f, a2 = 0.f, a3 = 0.f;
#pragma unroll 4
    for (int k = 0; k < NIN; k++) {
        float w = W[k * NHID + n];
        a0 += sx[0][k] * w; a1 += sx[1][k] * w;
        a2 += sx[2][k] * w; a3 += sx[3][k] * w;
    }
    d_inp[n*64 + b0 + 0] = a0;
    d_inp[n*64 + b0 + 1] = a1;
    d_inp[n*64 + b0 + 2] = a2;
    d_inp[n*64 + b0 + 3] = a3;
}

// ---------------- grid barrier ----------------
__device__ __forceinline__ void gridbar() {
    __syncthreads();
    if (threadIdx.x == 0) {
        __threadfence();
        unsigned gen = g_gen;
        if (atomicInc(&g_cnt, NBLK - 1) == NBLK - 1) {
            __threadfence();
            g_gen = gen + 1;
        } else {
            while (g_gen == gen) __nanosleep(64);
        }
        __threadfence();
    }
    __syncthreads();
}

// ---------------- phases ----------------
__device__ __forceinline__ void neuron_phase(int u, int gtid) {
    int buf = u & 1;
    int slot = u & 15;
    bool inject = (u % 3) == 2;
#pragma unroll
    for (int k = 0; k < 2; k++) {
        int idx = gtid + k * TPG;
        if (idx >= NELEM) break;
        int n = idx >> 6, b = idx & 63;
        float I = d_ring[slot * NELEM + idx];
        d_ring[slot * NELEM + idx] = 0.f;
        if (inject && n < NHID) I += d_inp[idx];
        float vm = d_vm[idx];
        vm += (I - vm) * 0.1f;
        float ve = fmaxf(0.f, vm - 0.25f);
        bool fired = (ve > 0.f) && (n < NHID);
        if (n >= NHID) d_acc[(n - NHID) * 64 + b] += vm;
        d_vm[idx] = fired ? -0.2f : vm;
        if (n < NHID) d_vexc[buf][idx] = ve;
        uint32_t bal = __ballot_sync(0xffffffffu, fired);
        if (((threadIdx.x & 31) == 0) && n < NHID)
            d_fired[buf][n * 2 + ((idx >> 5) & 1)] = bal;
    }
}

__device__ __forceinline__ void edge_phase(int u) {
    int buf = u & 1;
    int w = blockIdx.x * (NTHR / 32) + (threadIdx.x >> 5);
    int lane = threadIdx.x & 31;
    int e0 = w * EPW;
    int e1 = e0 + EPW; if (e1 > NE) e1 = NE;
    const int half = lane >> 4;
    const int sh = (lane * 2) & 31;
    ushort* cptr = (ushort*)d_cnt;
#pragma unroll 2
    for (int e = e0; e < e1; e++) {
        uint32_t m = d_meta[e];
        ushort c = cptr[e * 32 + lane];
        int srcn = m & 2047;
        uint32_t f2 = (d_fired[buf][srcn * 2 + half] >> sh) & 3u;
        uint32_t c0 = c & 255u, c1 = c >> 8;
        uint32_t dly = m >> 23;
        bool l0 = (c0 == 0u) && (f2 & 1u);
        bool l1 = (c1 == 0u) && (f2 & 2u);
        uint32_t n0 = c0 ? (c0 - 1u) : (l0 ? dly : 0u);
        uint32_t n1 = c1 ? (c1 - 1u) : (l1 ? dly : 0u);
        ushort nc = (ushort)(n0 | (n1 << 8));
        if (nc != c) cptr[e * 32 + lane] = nc;
        if (l0 | l1) {
            float wgt = d_wgt[e];
            int tg = (m >> 11) & 4095;
            float* dst = &d_ring[(((unsigned)u + dly) & 15u) * NELEM + tg * 64 + 2 * lane];
            if (l0) atomicAdd(dst,     wgt * d_vexc[buf][srcn * 64 + 2 * lane]);
            if (l1) atomicAdd(dst + 1, wgt * d_vexc[buf][srcn * 64 + 2 * lane + 1]);
        }
    }
}

// ---------------- persistent simulation kernel ----------------
__global__ void __launch_bounds__(NTHR, 1) sim_kernel(float* __restrict__ out) {
    int gtid = blockIdx.x * NTHR + threadIdx.x;
    neuron_phase(0, gtid);
    gridbar();
    for (int u = 0; u < TSTEPS; u++) {
        edge_phase(u);
        if (u + 1 < TSTEPS) neuron_phase(u + 1, gtid);
        gridbar();
    }
    // write out[b*10+o] = acc[o*64+b]/30
    if (gtid < NOUT * BATCH) {
        int o = gtid >> 6, b = gtid & 63;
        out[b * NOUT + o] = d_acc[o * 64 + b] * (1.0f / (float)TSTEPS);
    }
}

extern "C" void kernel_launch(void* const* d_in, const int* in_sizes, int n_in,
                              void* d_out, int out_size) {
    const float* x   = (const float*)d_in[0];
    const float* W   = (const float*)d_in[1];
    const float* We  = (const float*)d_in[2];
    const float* Le  = (const float*)d_in[3];
    const int*   src = (const int*)d_in[4];
    const int*   tgt = (const int*)d_in[5];
    float* out = (float*)d_out;
    (void)in_sizes; (void)n_in; (void)out_size;

    init_kernel<<<1024, 256>>>(We, Le, src, tgt);
    dim3 gg(8, 16);
    gemm_kernel<<<gg, 256>>>(x, W);
    sim_kernel<<<NBLK, NTHR>>>(out);
}

// round 3
// speedup vs baseline: 1.7547x; 1.7547x over previous
#include <cuda_runtime.h>
#include <stdint.h>

#define BATCH  64
#define NIN    784
#define NHID   2048
#define NOUT   10
#define NN     2058
#define NE     262144
#define TSTEPS 30
#define NBLK   148
#define NTHR   512
#define WPB    (NTHR/32)        // 16 warps/block
#define EPW    111              // edges per warp
#define EPB    (WPB*EPW)        // 1776 edges per block (148*1776 = 262848 >= NE)
#define NELEM  (NN*BATCH)       // 131712
#define TPG    (NBLK*NTHR)      // 75776

// smem layout (bytes)
#define S_CNT_B   (EPB*64)                  // 113664: ushort cnt[EPB][32]
#define S_META_B  (EPB*4)                   // 7104
#define S_WGT_B   (EPB*4)                   // 7104
#define S_FIRED_B (NHID*2*4)                // 16384
#define SMEM_B    (S_CNT_B+S_META_B+S_WGT_B+S_FIRED_B)  // 144256

// ---------------- static device state ----------------
__device__ float    d_ring[16*NELEM];         // future current ring [slot][n*64+b]
__device__ float    d_vm[NELEM];
__device__ float    d_vexc[2][NHID*BATCH];
__device__ uint32_t d_fired[2][NHID*2];
__device__ float    d_acc[NOUT*BATCH];
__device__ float    d_inp[NHID*BATCH];
__device__ unsigned g_cnt = 0;
__device__ volatile unsigned g_gen = 0;

// ---------------- init: zero ring/vm/acc ----------------
__global__ void init_kernel() {
    int g = blockIdx.x * blockDim.x + threadIdx.x;
    int st = gridDim.x * blockDim.x;
    float4 z = make_float4(0.f, 0.f, 0.f, 0.f);
    float4* r4 = (float4*)d_ring;
    for (int i = g; i < 16*NELEM/4; i += st) r4[i] = z;
    float4* v4 = (float4*)d_vm;
    for (int i = g; i < NELEM/4; i += st) v4[i] = z;
    for (int i = g; i < NOUT*BATCH; i += st) d_acc[i] = 0.f;
}

// ---------------- input currents: inp[n*64+b] ----------------
__global__ void gemm_kernel(const float* __restrict__ x, const float* __restrict__ W) {
    __shared__ float sx[4][NIN];
    int n  = blockIdx.x * 256 + threadIdx.x;
    int b0 = blockIdx.y * 4;
    for (int i = threadIdx.x; i < 4*NIN; i += 256) {
        int bb = i / NIN, kk = i - bb * NIN;
        sx[bb][kk] = x[(b0 + bb) * NIN + kk];
    }
    __syncthreads();
    float a0 = 0.f, a1 = 0.f, a2 = 0.f, a3 = 0.f;
#pragma unroll 4
    for (int k = 0; k < NIN; k++) {
        float w = W[k * NHID + n];
        a0 += sx[0][k] * w; a1 += sx[1][k] * w;
        a2 += sx[2][k] * w; a3 += sx[3][k] * w;
    }
    d_inp[n*64 + b0 + 0] = a0;
    d_inp[n*64 + b0 + 1] = a1;
    d_inp[n*64 + b0 + 2] = a2;
    d_inp[n*64 + b0 + 3] = a3;
}

// ---------------- grid barrier ----------------
__device__ __forceinline__ void gridbar() {
    __syncthreads();
    if (threadIdx.x == 0) {
        __threadfence();
        unsigned gen = g_gen;
        if (atomicInc(&g_cnt, NBLK - 1) == NBLK - 1) {
            __threadfence();
            g_gen = gen + 1;
        } else {
            while (g_gen == gen) __nanosleep(64);
        }
        __threadfence();
    }
    __syncthreads();
}

// ---------------- neuron phase (step u) ----------------
__device__ __forceinline__ void neuron_phase(int u, int gtid) {
    int buf = u & 1;
    int slot = u & 15;
    bool inject = (u % 3) == 2;
#pragma unroll
    for (int k = 0; k < 2; k++) {
        int idx = gtid + k * TPG;
        if (idx >= NELEM) break;
        int n = idx >> 6, b = idx & 63;
        float I = d_ring[slot * NELEM + idx];
        d_ring[slot * NELEM + idx] = 0.f;
        if (inject && n < NHID) I += d_inp[idx];
        float vm = d_vm[idx];
        vm += (I - vm) * 0.1f;
        float ve = fmaxf(0.f, vm - 0.25f);
        bool fired = (ve > 0.f) && (n < NHID);
        if (n >= NHID) d_acc[(n - NHID) * 64 + b] += vm;
        d_vm[idx] = fired ? -0.2f : vm;
        if (n < NHID) d_vexc[buf][idx] = ve;
        uint32_t bal = __ballot_sync(0xffffffffu, fired);
        if (((threadIdx.x & 31) == 0) && n < NHID)
            d_fired[buf][n * 2 + ((idx >> 5) & 1)] = bal;
    }
}

// ---------------- edge phase (step u), smem-resident ----------------
__device__ __forceinline__ bool edge_phase(int u, bool warp_active, bool any_fired,
                                           ushort* __restrict__ s_cnt,
                                           const uint32_t* __restrict__ s_meta,
                                           const float* __restrict__ s_wgt,
                                           const uint32_t* __restrict__ s_fired) {
    if (!warp_active && !any_fired) return false;
    int wid = threadIdx.x >> 5, lane = threadIdx.x & 31;
    int e0 = wid * EPW;
    int e1 = e0 + EPW;
    int lim = NE - blockIdx.x * EPB;
    if (e1 > lim) e1 = lim;
    int buf = u & 1;
    const int half = lane >> 4;
    const int sh = (lane * 2) & 31;
    bool act = false;
#pragma unroll 4
    for (int e = e0; e < e1; e++) {
        uint32_t m = s_meta[e];
        ushort c = s_cnt[e * 32 + lane];
        uint32_t srcn = m & 2047u;
        uint32_t f2 = any_fired ? ((s_fired[srcn * 2 + half] >> sh) & 3u) : 0u;
        uint32_t c0 = c & 255u, c1 = c >> 8;
        uint32_t dly = m >> 23;
        bool l0 = (c0 == 0u) && (f2 & 1u);
        bool l1 = (c1 == 0u) && (f2 & 2u);
        uint32_t n0 = c0 ? (c0 - 1u) : (l0 ? dly : 0u);
        uint32_t n1 = c1 ? (c1 - 1u) : (l1 ? dly : 0u);
        ushort nc = (ushort)(n0 | (n1 << 8));
        if (nc != c) s_cnt[e * 32 + lane] = nc;
        act |= (nc != 0);
        if (l0 | l1) {
            float wgt = s_wgt[e];
            float2 ve = ((const float2*)(d_vexc[buf] + srcn * 64))[lane];
            float* dst = &d_ring[(((unsigned)u + dly) & 15u) * NELEM
                                 + (((m >> 11) & 4095u) << 6) + 2 * lane];
            if (l0) atomicAdd(dst,     wgt * ve.x);
            if (l1) atomicAdd(dst + 1, wgt * ve.y);
        }
    }
    return __any_sync(0xffffffffu, act);
}

// ---------------- persistent simulation kernel ----------------
__global__ void __launch_bounds__(NTHR, 1) sim_kernel(
        const float* __restrict__ We, const float* __restrict__ Le,
        const int* __restrict__ src, const int* __restrict__ tgt,
        float* __restrict__ out) {
    extern __shared__ uint8_t smem[];
    ushort*   s_cnt   = (ushort*)smem;
    uint32_t* s_meta  = (uint32_t*)(smem + S_CNT_B);
    float*    s_wgt   = (float*)(smem + S_CNT_B + S_META_B);
    uint32_t* s_fired = (uint32_t*)(smem + S_CNT_B + S_META_B + S_WGT_B);

    int gtid = blockIdx.x * NTHR + threadIdx.x;

    // prologue: zero counters, build per-block edge tables in smem
    uint32_t* c32 = (uint32_t*)s_cnt;
    for (int i = threadIdx.x; i < S_CNT_B/4; i += NTHR) c32[i] = 0u;
    for (int i = threadIdx.x; i < EPB; i += NTHR) {
        int ge = blockIdx.x * EPB + i;
        if (ge < NE) {
            int d = (int)(Le[ge] * 2.0f + 0.5f);    // 6..15
            s_meta[i] = (uint32_t)src[ge] | ((uint32_t)tgt[ge] << 11) | ((uint32_t)d << 23);
            s_wgt[i]  = We[ge];
        }
    }
    __syncthreads();

    bool wact = false;
    neuron_phase(0, gtid);
    gridbar();
    for (int u = 0; u < TSTEPS; u++) {
        int buf = u & 1;
        uint32_t facc = 0u;
#pragma unroll
        for (int i = threadIdx.x; i < NHID*2; i += NTHR) {
            uint32_t v = d_fired[buf][i];
            s_fired[i] = v;
            facc |= v;
        }
        int anyf = __syncthreads_or((int)(facc != 0u));
        wact = edge_phase(u, wact, anyf != 0, s_cnt, s_meta, s_wgt, s_fired);
        if (u + 1 < TSTEPS) neuron_phase(u + 1, gtid);
        gridbar();
    }
    if (gtid < NOUT * BATCH) {
        int o = gtid >> 6, b = gtid & 63;
        out[b * NOUT + o] = d_acc[o * 64 + b] * (1.0f / (float)TSTEPS);
    }
}

extern "C" void kernel_launch(void* const* d_in, const int* in_sizes, int n_in,
                              void* d_out, int out_size) {
    const float* x   = (const float*)d_in[0];
    const float* W   = (const float*)d_in[1];
    const float* We  = (const float*)d_in[2];
    const float* Le  = (const float*)d_in[3];
    const int*   src = (const int*)d_in[4];
    const int*   tgt = (const int*)d_in[5];
    float* out = (float*)d_out;
    (void)in_sizes; (void)n_in; (void)out_size;

    cudaFuncSetAttribute(sim_kernel, cudaFuncAttributeMaxDynamicSharedMemorySize, SMEM_B);

    init_kernel<<<2048, 256>>>();
    dim3 gg(8, 16);
    gemm_kernel<<<gg, 256>>>(x, W);
    sim_kernel<<<NBLK, NTHR, SMEM_B>>>(We, Le, src, tgt, out);
}

// round 4
// speedup vs baseline: 1.9528x; 1.1129x over previous
#include <cuda_runtime.h>
#include <stdint.h>

#define BATCH  64
#define NIN    784
#define NHID   2048
#define NOUT   10
#define NN     2058
#define NE     262144
#define TSTEPS 30
#define NBLK   148
#define NTHR   512
#define WPB    (NTHR/32)        // 16 warps/block
#define EPW    112              // edges per warp (even)
#define EPB    (WPB*EPW)        // 1792 edges/block; 148*1792 >= NE
#define NELEM  (NN*BATCH)       // 131712
#define TPG    (NBLK*NTHR)      // 75776
#define NPB    14               // n-columns of input GEMM per block (148*14 >= 2048)

// smem layout (bytes)
#define S_CNT_B   (EPB*64)                  // 114688: u8 cnt[EPB][64] as u32[EPB][16]
#define S_META_B  (EPB*4)                   // 7168
#define S_WGT_B   (EPB*4)                   // 7168
#define S_FIRED_B (NHID*2*4)                // 16384
#define SMEM_B    (S_CNT_B+S_META_B+S_WGT_B+S_FIRED_B)  // 145408

// ---------------- static device state ----------------
__device__ __align__(16) float    d_ring[16*NELEM];     // future current ring [slot][n*64+b]
__device__ __align__(16) float    d_vm[NELEM];
__device__ __align__(16) float    d_vexc[2][NHID*BATCH];
__device__ uint32_t d_fired[2][NHID*2];
__device__ float    d_acc[NOUT*BATCH];
__device__ __align__(16) float    d_inp[NHID*BATCH];
__device__ unsigned g_cnt = 0;
__device__ volatile unsigned g_gen = 0;

// ---------------- grid barrier ----------------
__device__ __forceinline__ void gridbar() {
    __syncthreads();
    if (threadIdx.x == 0) {
        __threadfence();
        unsigned gen = g_gen;
        if (atomicInc(&g_cnt, NBLK - 1) == NBLK - 1) {
            __threadfence();
            g_gen = gen + 1;
        } else {
            while (g_gen == gen) __nanosleep(64);
        }
        __threadfence();
    }
    __syncthreads();
}

// ---------------- neuron phase (step u) ----------------
__device__ __forceinline__ void neuron_phase(int u, int gtid) {
    int buf = u & 1;
    int slot = u & 15;
    bool inject = (u % 3) == 2;
#pragma unroll
    for (int k = 0; k < 2; k++) {
        int idx = gtid + k * TPG;
        if (idx >= NELEM) break;
        int n = idx >> 6, b = idx & 63;
        float I = d_ring[slot * NELEM + idx];
        d_ring[slot * NELEM + idx] = 0.f;
        if (inject && n < NHID) I += d_inp[idx];
        float vm = d_vm[idx];
        vm += (I - vm) * 0.1f;
        float ve = fmaxf(0.f, vm - 0.25f);
        bool fired = (ve > 0.f) && (n < NHID);
        if (n >= NHID) d_acc[(n - NHID) * 64 + b] += vm;
        d_vm[idx] = fired ? -0.2f : vm;
        if (n < NHID) d_vexc[buf][idx] = ve;
        uint32_t bal = __ballot_sync(0xffffffffu, fired);
        if (((threadIdx.x & 31) == 0) && n < NHID)
            d_fired[buf][n * 2 + ((idx >> 5) & 1)] = bal;
    }
}

// ---------------- edge phase (step u): byte-SIMD, smem-resident ----------------
__device__ __forceinline__ bool edge_phase(int u, bool warp_active, bool any_fired,
                                           uint32_t* __restrict__ cnt32,
                                           const uint32_t* __restrict__ s_meta,
                                           const float* __restrict__ s_wgt,
                                           const uint32_t* __restrict__ s_fired) {
    if (!warp_active && !any_fired) return false;
    int wid = threadIdx.x >> 5, lane = threadIdx.x & 31;
    int e0 = wid * EPW;
    int e1 = e0 + EPW;
    int lim = NE - blockIdx.x * EPB;
    if (lim < 0) lim = 0;
    if (e1 > lim) e1 = lim;
    int buf = u & 1;
    const int sub  = lane >> 4;       // which edge of the pair
    const int q    = lane & 15;       // batch quartet: b0 = q*4
    const int word = q >> 3;
    const int shift = (q & 7) * 4;
    uint32_t act = 0u;
#pragma unroll 4
    for (int e = e0 + sub; e < e1; e += 2) {
        uint32_t m = s_meta[e];
        uint32_t c = cnt32[e * 16 + q];
        uint32_t srcn = m & 2047u;
        uint32_t f4 = any_fired ? ((s_fired[srcn * 2 + word] >> shift) & 15u) : 0u;
        uint32_t fm = ((f4 * 0x00204081u) & 0x01010101u) * 0xFFu;
        uint32_t lm = __vcmpeq4(c, 0u) & fm;
        uint32_t dly = m >> 23;
        uint32_t nc = __vsubus4(c, 0x01010101u) | (lm & (dly * 0x01010101u));
        cnt32[e * 16 + q] = nc;
        act |= nc;
        if (lm) {
            float wgt = s_wgt[e];
            const float4 ve = ((const float4*)(d_vexc[buf] + srcn * 64))[q];
            float* dst = &d_ring[(((unsigned)u + dly) & 15u) * NELEM
                                 + (((m >> 11) & 4095u) << 6) + q * 4];
            if (lm & 0x000000FFu) atomicAdd(dst + 0, wgt * ve.x);
            if (lm & 0x0000FF00u) atomicAdd(dst + 1, wgt * ve.y);
            if (lm & 0x00FF0000u) atomicAdd(dst + 2, wgt * ve.z);
            if (lm & 0xFF000000u) atomicAdd(dst + 3, wgt * ve.w);
        }
    }
    return __any_sync(0xffffffffu, act != 0u);
}

// ---------------- fused kernel: init + input GEMM + simulation ----------------
__global__ void __launch_bounds__(NTHR, 1) sim_kernel(
        const float* __restrict__ x,  const float* __restrict__ W,
        const float* __restrict__ We, const float* __restrict__ Le,
        const int* __restrict__ src,  const int* __restrict__ tgt,
        float* __restrict__ out) {
    extern __shared__ uint8_t smem[];
    uint32_t* cnt32   = (uint32_t*)smem;
    uint32_t* s_meta  = (uint32_t*)(smem + S_CNT_B);
    float*    s_wgt   = (float*)(smem + S_CNT_B + S_META_B);
    uint32_t* s_fired = (uint32_t*)(smem + S_CNT_B + S_META_B + S_WGT_B);

    int tid  = threadIdx.x;
    int gtid = blockIdx.x * NTHR + tid;

    // ---- zero global state (grid-strided) ----
    {
        float4 z = make_float4(0.f, 0.f, 0.f, 0.f);
        float4* r4 = (float4*)d_ring;
        for (int i = gtid; i < 16*NELEM/4; i += TPG) r4[i] = z;
        float4* v4 = (float4*)d_vm;
        for (int i = gtid; i < NELEM/4; i += TPG) v4[i] = z;
        if (gtid < NOUT*BATCH) d_acc[gtid] = 0.f;
    }

    // ---- input GEMM: d_inp[n*64+b] = sum_k x[b,k]*W[k,n]; block owns NPB n's ----
    {
        float* sxT = (float*)smem;                 // [392][64] staging (100KB)
        int n0 = blockIdx.x * NPB;
        int b  = tid & 63;
        int nl0 = tid >> 6;                        // 0..7
        int nl1 = 8 + (tid >> 6);                  // 8..15 (valid for tid<384 -> nl1<=13)
        bool v0 = (n0 + nl0 < NHID);
        bool v1 = (tid < (NPB-8)*64) && (n0 + nl1 < NHID);
        float a0 = 0.f, a1 = 0.f;
#pragma unroll
        for (int h = 0; h < 2; h++) {
            int k0 = h * 392;
            __syncthreads();
            for (int i = tid; i < 392*64; i += NTHR) {
                int bb = i / 392, kk = i - bb * 392;
                sxT[kk * 64 + bb] = x[bb * NIN + k0 + kk];
            }
            __syncthreads();
#pragma unroll 4
            for (int kk = 0; kk < 392; kk++) {
                float xv = sxT[kk * 64 + b];
                float w0 = v0 ? W[(k0 + kk) * NHID + n0 + nl0] : 0.f;
                float w1 = v1 ? W[(k0 + kk) * NHID + n0 + nl1] : 0.f;
                a0 += xv * w0;
                a1 += xv * w1;
            }
        }
        if (v0) d_inp[(n0 + nl0) * 64 + b] = a0;
        if (v1) d_inp[(n0 + nl1) * 64 + b] = a1;
        __syncthreads();
    }

    // ---- build per-block edge tables, zero counters ----
    for (int i = tid; i < S_CNT_B/4; i += NTHR) cnt32[i] = 0u;
    for (int i = tid; i < EPB; i += NTHR) {
        int ge = blockIdx.x * EPB + i;
        if (ge < NE) {
            int d = (int)(Le[ge] * 2.0f + 0.5f);    // 6..15
            s_meta[i] = (uint32_t)src[ge] | ((uint32_t)tgt[ge] << 11) | ((uint32_t)d << 23);
            s_wgt[i]  = We[ge];
        }
    }
    gridbar();                                      // ring/vm zero + inp visible everywhere

    // ---- simulation ----
    bool wact = false;
    neuron_phase(0, gtid);
    gridbar();
    for (int u = 0; u < TSTEPS; u++) {
        int buf = u & 1;
        uint32_t facc = 0u;
#pragma unroll
        for (int i = tid; i < NHID*2; i += NTHR) {
            uint32_t v = d_fired[buf][i];
            s_fired[i] = v;
            facc |= v;
        }
        int anyf = __syncthreads_or((int)(facc != 0u));
        wact = edge_phase(u, wact, anyf != 0, cnt32, s_meta, s_wgt, s_fired);
        if (u + 1 < TSTEPS) neuron_phase(u + 1, gtid);
        gridbar();
    }
    if (gtid < NOUT * BATCH) {
        int o = gtid >> 6, b = gtid & 63;
        out[b * NOUT + o] = d_acc[o * 64 + b] * (1.0f / (float)TSTEPS);
    }
}

extern "C" void kernel_launch(void* const* d_in, const int* in_sizes, int n_in,
                              void* d_out, int out_size) {
    const float* x   = (const float*)d_in[0];
    const float* W   = (const float*)d_in[1];
    const float* We  = (const float*)d_in[2];
    const float* Le  = (const float*)d_in[3];
    const int*   src = (const int*)d_in[4];
    const int*   tgt = (const int*)d_in[5];
    float* out = (float*)d_out;
    (void)in_sizes; (void)n_in; (void)out_size;

    cudaFuncSetAttribute(sim_kernel, cudaFuncAttributeMaxDynamicSharedMemorySize, SMEM_B);
    sim_kernel<<<NBLK, NTHR, SMEM_B>>>(x, W, We, Le, src, tgt, out);
}

// round 6
// speedup vs baseline: 2.1504x; 1.1012x over previous
#include <cuda_runtime.h>
#include <stdint.h>

#define BATCH  64
#define NIN    784
#define NHID   2048
#define NOUT   10
#define NN     2058
#define NE     262144
#define TSTEPS 30
#define NBLK   148
#define NTHR   512
#define WPB    16
#define NCLS   (NHID*10)                 // 20480 classes (src, delay)
#define CPB    ((NCLS + NBLK - 1)/NBLK)  // 139 classes per block

// ---------------- static device state ----------------
__device__ __align__(16) float    d_vexc[16*NHID*BATCH];  // vexc ring [slot][s*64+b]  (8.4MB)
__device__ uint32_t d_fired[2][NHID*2];                   // fired bitmaps, double-buffered
__device__ __align__(16) uint8_t  d_lmask[16*NCLS*16];    // launch nibbles [slot][cls][quartet] (5.2MB)
__device__ __align__(16) float    d_inp[NHID*BATCH];      // input currents [n*64+b]
__device__ uint32_t d_hist[NN];
__device__ uint32_t d_off[NN+1];
__device__ uint32_t d_cursor[NN];
__device__ uint16_t d_ecls[NE];                           // CSR by tgt: src | (d-6)<<11
__device__ float    d_ew[NE];                             // CSR weights
__device__ unsigned g_cnt = 0;
__device__ volatile unsigned g_gen = 0;

// ---------------- init kernels ----------------
__global__ void zero_kernel() {
    int g = blockIdx.x * blockDim.x + threadIdx.x;
    int st = gridDim.x * blockDim.x;
    uint32_t* lm = (uint32_t*)d_lmask;
    for (int i = g; i < 16*NCLS*16/4; i += st) lm[i] = 0u;
    for (int i = g; i < NN; i += st) d_hist[i] = 0u;
}

__global__ void hist_kernel(const int* __restrict__ tgt) {
    int e = blockIdx.x * blockDim.x + threadIdx.x;
    if (e < NE) atomicAdd(&d_hist[tgt[e]], 1u);
}

__global__ void scan_kernel() {
    __shared__ uint32_t sa[NN], sb[NN];
    int tid = threadIdx.x;
    for (int i = tid; i < NN; i += 1024) sa[i] = d_hist[i];
    __syncthreads();
    uint32_t *pin = sa, *pout = sb;
    for (int off = 1; off < NN; off <<= 1) {
        for (int i = tid; i < NN; i += 1024)
            pout[i] = pin[i] + (i >= off ? pin[i - off] : 0u);
        __syncthreads();
        uint32_t* t = pin; pin = pout; pout = t;
    }
    for (int i = tid; i < NN; i += 1024) {
        d_off[i+1]  = pin[i];
        d_cursor[i] = (i > 0) ? pin[i-1] : 0u;
    }
    if (tid == 0) d_off[0] = 0u;
}

__global__ void scatter_kernel(const float* __restrict__ We, const float* __restrict__ Le,
                               const int* __restrict__ src, const int* __restrict__ tgt) {
    int e = blockIdx.x * blockDim.x + threadIdx.x;
    if (e >= NE) return;
    int d = (int)(Le[e] * 2.0f + 0.5f);        // 6..15
    uint32_t pos = atomicAdd(&d_cursor[tgt[e]], 1u);
    d_ecls[pos] = (uint16_t)((uint32_t)src[e] | ((uint32_t)(d - 6) << 11));
    d_ew[pos] = We[e];
}

// ---------------- input GEMM: d_inp[n*64+b] = sum_k x[b,k] W[k,n] ----------------
__global__ void gemm_kernel(const float* __restrict__ x, const float* __restrict__ W) {
    __shared__ float sx[4][NIN];
    int n  = blockIdx.x * 256 + threadIdx.x;
    int b0 = blockIdx.y * 4;
    for (int i = threadIdx.x; i < 4*NIN; i += 256) {
        int bb = i / NIN, kk = i - bb * NIN;
        sx[bb][kk] = x[(b0 + bb) * NIN + kk];
    }
    __syncthreads();
    float a0 = 0.f, a1 = 0.f, a2 = 0.f, a3 = 0.f;
#pragma unroll 4
    for (int k = 0; k < NIN; k++) {
        float w = W[k * NHID + n];
        a0 += sx[0][k] * w; a1 += sx[1][k] * w;
        a2 += sx[2][k] * w; a3 += sx[3][k] * w;
    }
    d_inp[n*64 + b0 + 0] = a0;
    d_inp[n*64 + b0 + 1] = a1;
    d_inp[n*64 + b0 + 2] = a2;
    d_inp[n*64 + b0 + 3] = a3;
}

// ---------------- grid barrier ----------------
__device__ __forceinline__ void gridbar() {
    __syncthreads();
    if (threadIdx.x == 0) {
        __threadfence();
        unsigned gen = g_gen;
        if (atomicInc(&g_cnt, NBLK - 1) == NBLK - 1) {
            __threadfence();
            g_gen = gen + 1;
        } else {
            while (g_gen == gen) __nanosleep(64);
        }
        __threadfence();
    }
    __syncthreads();
}

__device__ __forceinline__ uint32_t spread16(uint32_t x) {
    x &= 0xFFFFu;
    x = (x | (x << 8)) & 0x00FF00FFu;
    x = (x | (x << 4)) & 0x0F0F0F0Fu;
    x = (x | (x << 2)) & 0x33333333u;
    x = (x | (x << 1)) & 0x55555555u;
    return x;
}

// ---------------- launch phase (step u): class counters in smem ----------------
// Writes launch nibbles into slot u&15 (launch-time indexed, matching vexc ring).
__device__ __forceinline__ void launch_phase(int u, const uint32_t* __restrict__ s_cmeta,
                                             uint32_t* __restrict__ scnt) {
    int wid = threadIdx.x >> 5, lane = threadIdx.x & 31;
    int sub = lane >> 4, q = lane & 15;
    int buf = u & 1;
    int wslot = u & 15;
#pragma unroll
    for (int k = 0; k < 5; k++) {
        int cl = k * 32 + wid * 2 + sub;
        if (cl >= CPB) break;
        uint32_t cm = s_cmeta[cl];
        if (cm == 0xFFFFFFFFu) continue;
        uint32_t s = cm & 0xFFFFu, d = cm >> 16;
        uint32_t fw = __ldcg(&d_fired[buf][s*2 + (q >> 3)]);
        uint32_t f4 = (fw >> ((q & 7) * 4)) & 15u;
        uint32_t c = scnt[cl*16 + q];
        uint32_t fm = ((f4 * 0x00204081u) & 0x01010101u) * 0xFFu;
        uint32_t lm = __vcmpeq4(c, 0u) & fm;
        scnt[cl*16 + q] = __vsubus4(c, 0x01010101u) | (lm & (d * 0x01010101u));
        uint32_t xb = lm & 0x01010101u;
        uint32_t nib = (xb | (xb >> 7) | (xb >> 14) | (xb >> 21)) & 15u;
        uint32_t cg = blockIdx.x * CPB + cl;
        d_lmask[(unsigned)wslot * (NCLS*16) + cg*16 + q] = (uint8_t)nib;
    }
}

// ---------------- neuron + delivery (step u): warp owns target n ----------------
__device__ __forceinline__ void neuron_phase(int u, int n,
        float& vm0, float& vm1, float& acc0, float& acc1) {
    if (n >= NN) return;
    int lane = threadIdx.x & 31;
    int q = lane >> 1, sh = (lane & 1) * 2;
    float I0 = 0.f, I1 = 0.f;
    int beg = d_off[n], end = d_off[n+1];
#pragma unroll 4
    for (int i = beg; i < end; i++) {
        uint32_t meta = (uint32_t)d_ecls[i];
        uint32_t s = meta & 2047u, dm6 = meta >> 11;
        uint32_t slot = ((unsigned)u - dm6 - 6u) & 15u;   // launch-time slot
        unsigned char nib = __ldcg((const unsigned char*)
            &d_lmask[slot * (NCLS*16) + (s*10u + dm6)*16 + q]);
        if (__any_sync(0xffffffffu, nib)) {
            float w = d_ew[i];
            float2 ve = __ldcg((const float2*)&d_vexc[slot * (NHID*64) + s*64 + 2*lane]);
            if (nib & (1u << sh)) I0 += w * ve.x;
            if (nib & (2u << sh)) I1 += w * ve.y;
        }
    }
    bool hid = n < NHID;
    if (hid && (u % 3) == 2) {
        float2 ip = *(const float2*)&d_inp[n*64 + 2*lane];
        I0 += ip.x; I1 += ip.y;
    }
    vm0 += (I0 - vm0) * 0.1f;
    vm1 += (I1 - vm1) * 0.1f;
    if (!hid) { acc0 += vm0; acc1 += vm1; return; }
    float ve0 = fmaxf(0.f, vm0 - 0.25f);
    float ve1 = fmaxf(0.f, vm1 - 0.25f);
    bool f0 = ve0 > 0.f, f1 = ve1 > 0.f;
    if (f0) vm0 = -0.2f;
    if (f1) vm1 = -0.2f;
    int slot = u & 15, buf = u & 1;
    *(float2*)&d_vexc[slot * (NHID*64) + n*64 + 2*lane] = make_float2(ve0, ve1);
    uint32_t b0 = __ballot_sync(0xffffffffu, f0);
    uint32_t b1 = __ballot_sync(0xffffffffu, f1);
    uint32_t w0 = spread16(b0 & 0xFFFFu) | (spread16(b1 & 0xFFFFu) << 1);
    uint32_t w1 = spread16(b0 >> 16)     | (spread16(b1 >> 16) << 1);
    if (lane == 0) d_fired[buf][n*2]     = w0;
    if (lane == 1) d_fired[buf][n*2 + 1] = w1;
}

// ---------------- persistent simulation kernel ----------------
__global__ void __launch_bounds__(NTHR, 1) sim_kernel(float* __restrict__ out) {
    __shared__ uint32_t scnt[CPB*16];     // class counters: u8 x 4 batches per u32
    __shared__ uint32_t s_cmeta[CPB];
    int tid = threadIdx.x;
    for (int i = tid; i < CPB*16; i += NTHR) scnt[i] = 0u;
    for (int i = tid; i < CPB; i += NTHR) {
        uint32_t cg = blockIdx.x * CPB + i;
        s_cmeta[i] = (cg < NCLS) ? ((cg / 10u) | (((cg % 10u) + 6u) << 16)) : 0xFFFFFFFFu;
    }
    __syncthreads();

    int n = blockIdx.x * WPB + (tid >> 5);
    float vm0 = 0.f, vm1 = 0.f, acc0 = 0.f, acc1 = 0.f;

    neuron_phase(0, n, vm0, vm1, acc0, acc1);
    gridbar();
    for (int u = 0; u < TSTEPS; u++) {
        launch_phase(u, s_cmeta, scnt);
        if (u + 1 < TSTEPS) neuron_phase(u + 1, n, vm0, vm1, acc0, acc1);
        gridbar();
    }
    if (n >= NHID && n < NN) {
        int lane = tid & 31;
        int o = n - NHID;
        out[(2*lane)   * NOUT + o] = acc0 * (1.0f / (float)TSTEPS);
        out[(2*lane+1) * NOUT + o] = acc1 * (1.0f / (float)TSTEPS);
    }
}

extern "C" void kernel_launch(void* const* d_in, const int* in_sizes, int n_in,
                              void* d_out, int out_size) {
    const float* x   = (const float*)d_in[0];
    const float* W   = (const float*)d_in[1];
    const float* We  = (const float*)d_in[2];
    const float* Le  = (const float*)d_in[3];
    const int*   src = (const int*)d_in[4];
    const int*   tgt = (const int*)d_in[5];
    float* out = (float*)d_out;
    (void)in_sizes; (void)n_in; (void)out_size;

    zero_kernel<<<1024, 256>>>();
    hist_kernel<<<NE/256, 256>>>(tgt);
    scan_kernel<<<1, 1024>>>();
    scatter_kernel<<<NE/256, 256>>>(We, Le, src, tgt);
    dim3 gg(8, 16);
    gemm_kernel<<<gg, 256>>>(x, W);
    sim_kernel<<<NBLK, NTHR>>>(out);
}

// round 7
// speedup vs baseline: 3.2615x; 1.5167x over previous
#include <cuda_runtime.h>
#include <stdint.h>

#define BATCH  64
#define NIN    784
#define NHID   2048
#define NOUT   10
#define NN     2058
#define NE     262144
#define TSTEPS 30
#define NBLK   148
#define NTHR   512
#define WPB    16
#define NCLS   (NHID*10)                 // 20480 classes (src, delay)
#define CPB    ((NCLS + NBLK - 1)/NBLK)  // 139 classes per block

// ---------------- static device state ----------------
__device__ __align__(16) float    d_vexc[16*NHID*BATCH];  // vexc ring [slot][s*64+b]
__device__ uint32_t d_fired[2][NHID*2];                   // fired bitmaps, double-buffered
__device__ __align__(16) uint8_t  d_lmask[16*NCLS*16];    // launch nibbles [slot][cls][quartet]
__device__ __align__(16) float    d_inp[NHID*BATCH];      // input currents [n*64+b]
__device__ uint32_t d_hist[NN];
__device__ uint32_t d_off[NN+1];
__device__ uint32_t d_cursor[NN];
__device__ __align__(16) uint2    d_edge[NE];             // CSR by tgt: {src|(d-6)<<11, w bits}
__device__ unsigned g_cnt = 0;
__device__ volatile unsigned g_gen = 0;

// ---------------- init + hist ----------------
__global__ void zero_hist_kernel(const int* __restrict__ tgt) {
    int g = blockIdx.x * blockDim.x + threadIdx.x;
    int st = gridDim.x * blockDim.x;
    uint32_t* lm = (uint32_t*)d_lmask;
    for (int i = g; i < 16*NCLS*16/4; i += st) lm[i] = 0u;
    for (int i = g; i < NN; i += st) d_hist[i] = 0u;
    __threadfence();
    // hist in a second grid-strided pass only safe if hist zeroed first -> do in scan? No:
    // separate loop ordering within same thread is fine only for its own elements.
    // So histogram is done in hist_kernel below.
}

__global__ void hist_kernel(const int* __restrict__ tgt) {
    int e = blockIdx.x * blockDim.x + threadIdx.x;
    if (e < NE) atomicAdd(&d_hist[tgt[e]], 1u);
}

__global__ void scan_kernel() {
    __shared__ uint32_t sa[NN], sb[NN];
    int tid = threadIdx.x;
    for (int i = tid; i < NN; i += 1024) sa[i] = d_hist[i];
    __syncthreads();
    uint32_t *pin = sa, *pout = sb;
    for (int off = 1; off < NN; off <<= 1) {
        for (int i = tid; i < NN; i += 1024)
            pout[i] = pin[i] + (i >= off ? pin[i - off] : 0u);
        __syncthreads();
        uint32_t* t = pin; pin = pout; pout = t;
    }
    for (int i = tid; i < NN; i += 1024) {
        d_off[i+1]  = pin[i];
        d_cursor[i] = (i > 0) ? pin[i-1] : 0u;
    }
    if (tid == 0) d_off[0] = 0u;
}

__global__ void scatter_kernel(const float* __restrict__ We, const float* __restrict__ Le,
                               const int* __restrict__ src, const int* __restrict__ tgt) {
    int e = blockIdx.x * blockDim.x + threadIdx.x;
    if (e >= NE) return;
    int d = (int)(Le[e] * 2.0f + 0.5f);        // 6..15
    uint32_t pos = atomicAdd(&d_cursor[tgt[e]], 1u);
    d_edge[pos] = make_uint2((uint32_t)src[e] | ((uint32_t)(d - 6) << 11),
                             __float_as_uint(We[e]));
}

// ---------------- input GEMM: d_inp[n*64+b] = sum_k x[b,k] W[k,n] ----------------
__global__ void gemm_kernel(const float* __restrict__ x, const float* __restrict__ W) {
    __shared__ float sx[4][NIN];
    int n  = blockIdx.x * 256 + threadIdx.x;
    int b0 = blockIdx.y * 4;
    for (int i = threadIdx.x; i < 4*NIN; i += 256) {
        int bb = i / NIN, kk = i - bb * NIN;
        sx[bb][kk] = x[(b0 + bb) * NIN + kk];
    }
    __syncthreads();
    float a0 = 0.f, a1 = 0.f, a2 = 0.f, a3 = 0.f;
#pragma unroll 4
    for (int k = 0; k < NIN; k++) {
        float w = W[k * NHID + n];
        a0 += sx[0][k] * w; a1 += sx[1][k] * w;
        a2 += sx[2][k] * w; a3 += sx[3][k] * w;
    }
    d_inp[n*64 + b0 + 0] = a0;
    d_inp[n*64 + b0 + 1] = a1;
    d_inp[n*64 + b0 + 2] = a2;
    d_inp[n*64 + b0 + 3] = a3;
}

// ---------------- grid barrier ----------------
__device__ __forceinline__ void gridbar() {
    __syncthreads();
    if (threadIdx.x == 0) {
        __threadfence();
        unsigned gen = g_gen;
        if (atomicInc(&g_cnt, NBLK - 1) == NBLK - 1) {
            __threadfence();
            g_gen = gen + 1;
        } else {
            while (g_gen == gen) __nanosleep(32);
        }
        __threadfence();
    }
    __syncthreads();
}

__device__ __forceinline__ uint32_t spread16(uint32_t x) {
    x &= 0xFFFFu;
    x = (x | (x << 8)) & 0x00FF00FFu;
    x = (x | (x << 4)) & 0x0F0F0F0Fu;
    x = (x | (x << 2)) & 0x33333333u;
    x = (x | (x << 1)) & 0x55555555u;
    return x;
}

// ---------------- launch phase (step u): class counters in smem ----------------
__device__ __forceinline__ void launch_phase(int u, const uint32_t* __restrict__ s_cmeta,
                                             uint32_t* __restrict__ scnt) {
    int wid = threadIdx.x >> 5, lane = threadIdx.x & 31;
    int sub = lane >> 4, q = lane & 15;
    int buf = u & 1;
    int wslot = u & 15;
#pragma unroll
    for (int k = 0; k < 5; k++) {
        int cl = k * 32 + wid * 2 + sub;
        if (cl >= CPB) break;
        uint32_t cm = s_cmeta[cl];
        if (cm == 0xFFFFFFFFu) continue;
        uint32_t s = cm & 0xFFFFu, d = cm >> 16;
        uint32_t fw = __ldcg(&d_fired[buf][s*2 + (q >> 3)]);
        uint32_t f4 = (fw >> ((q & 7) * 4)) & 15u;
        uint32_t c = scnt[cl*16 + q];
        uint32_t fm = ((f4 * 0x00204081u) & 0x01010101u) * 0xFFu;
        uint32_t lm = __vcmpeq4(c, 0u) & fm;
        scnt[cl*16 + q] = __vsubus4(c, 0x01010101u) | (lm & (d * 0x01010101u));
        uint32_t xb = lm & 0x01010101u;
        uint32_t nib = (xb | (xb >> 7) | (xb >> 14) | (xb >> 21)) & 15u;
        uint32_t cg = blockIdx.x * CPB + cl;
        d_lmask[(unsigned)wslot * (NCLS*16) + cg*16 + q] = (uint8_t)nib;
    }
}

// ---------------- neuron + delivery (step u): warp owns target n ----------------
__device__ __forceinline__ void neuron_phase(int u, int n, int beg, int end,
        float& vm0, float& vm1, float& acc0, float& acc1) {
    if (n >= NN) return;
    int lane = threadIdx.x & 31;
    int q = lane >> 1, sh = (lane & 1) * 2;
    float I0 = 0.f, I1 = 0.f;
#pragma unroll 8
    for (int i = beg; i < end; i++) {
        uint2 ed = d_edge[i];                     // uniform LDG.64
        uint32_t s = ed.x & 2047u, dm6 = ed.x >> 11;
        uint32_t slot = ((unsigned)u - dm6 - 6u) & 15u;
        unsigned char nib = __ldcg((const unsigned char*)
            &d_lmask[slot * (NCLS*16) + (s*10u + dm6)*16 + q]);
        uint32_t bits = ((uint32_t)nib >> sh) & 3u;
        if (bits) {
            float w = __uint_as_float(ed.y);
            float2 ve = __ldcg((const float2*)&d_vexc[slot * (NHID*64) + s*64 + 2*lane]);
            if (bits & 1u) I0 += w * ve.x;
            if (bits & 2u) I1 += w * ve.y;
        }
    }
    bool hid = n < NHID;
    if (hid && (u % 3) == 2) {
        float2 ip = *(const float2*)&d_inp[n*64 + 2*lane];
        I0 += ip.x; I1 += ip.y;
    }
    vm0 += (I0 - vm0) * 0.1f;
    vm1 += (I1 - vm1) * 0.1f;
    if (!hid) { acc0 += vm0; acc1 += vm1; return; }
    float ve0 = fmaxf(0.f, vm0 - 0.25f);
    float ve1 = fmaxf(0.f, vm1 - 0.25f);
    bool f0 = ve0 > 0.f, f1 = ve1 > 0.f;
    if (f0) vm0 = -0.2f;
    if (f1) vm1 = -0.2f;
    int slot = u & 15, buf = u & 1;
    *(float2*)&d_vexc[slot * (NHID*64) + n*64 + 2*lane] = make_float2(ve0, ve1);
    uint32_t b0 = __ballot_sync(0xffffffffu, f0);
    uint32_t b1 = __ballot_sync(0xffffffffu, f1);
    uint32_t w0 = spread16(b0 & 0xFFFFu) | (spread16(b1 & 0xFFFFu) << 1);
    uint32_t w1 = spread16(b0 >> 16)     | (spread16(b1 >> 16) << 1);
    if (lane == 0) d_fired[buf][n*2]     = w0;
    if (lane == 1) d_fired[buf][n*2 + 1] = w1;
}

// ---------------- persistent simulation kernel ----------------
__global__ void __launch_bounds__(NTHR, 1) sim_kernel(float* __restrict__ out) {
    __shared__ uint32_t scnt[CPB*16];
    __shared__ uint32_t s_cmeta[CPB];
    int tid = threadIdx.x;
    for (int i = tid; i < CPB*16; i += NTHR) scnt[i] = 0u;
    for (int i = tid; i < CPB; i += NTHR) {
        uint32_t cg = blockIdx.x * CPB + i;
        s_cmeta[i] = (cg < NCLS) ? ((cg / 10u) | (((cg % 10u) + 6u) << 16)) : 0xFFFFFFFFu;
    }
    __syncthreads();

    int n = blockIdx.x * WPB + (tid >> 5);
    int beg = 0, end = 0;
    if (n < NN) { beg = d_off[n]; end = d_off[n+1]; }
    float vm0 = 0.f, vm1 = 0.f, acc0 = 0.f, acc1 = 0.f;

    neuron_phase(0, n, beg, end, vm0, vm1, acc0, acc1);
    gridbar();
    for (int u = 0; u < TSTEPS; u++) {
        launch_phase(u, s_cmeta, scnt);
        if (u + 1 < TSTEPS) neuron_phase(u + 1, n, beg, end, vm0, vm1, acc0, acc1);
        gridbar();
    }
    if (n >= NHID && n < NN) {
        int lane = tid & 31;
        int o = n - NHID;
        out[(2*lane)   * NOUT + o] = acc0 * (1.0f / (float)TSTEPS);
        out[(2*lane+1) * NOUT + o] = acc1 * (1.0f / (float)TSTEPS);
    }
}

extern "C" void kernel_launch(void* const* d_in, const int* in_sizes, int n_in,
                              void* d_out, int out_size) {
    const float* x   = (const float*)d_in[0];
    const float* W   = (const float*)d_in[1];
    const float* We  = (const float*)d_in[2];
    const float* Le  = (const float*)d_in[3];
    const int*   src = (const int*)d_in[4];
    const int*   tgt = (const int*)d_in[5];
    float* out = (float*)d_out;
    (void)in_sizes; (void)n_in; (void)out_size;

    zero_hist_kernel<<<1024, 256>>>(tgt);
    hist_kernel<<<NE/256, 256>>>(tgt);
    scan_kernel<<<1, 1024>>>();
    scatter_kernel<<<NE/256, 256>>>(We, Le, src, tgt);
    dim3 gg(8, 16);
    gemm_kernel<<<gg, 256>>>(x, W);
    sim_kernel<<<NBLK, NTHR>>>(out);
}

// round 8
// speedup vs baseline: 4.2261x; 1.2958x over previous
#include <cuda_runtime.h>
#include <stdint.h>

#define BATCH  64
#define NIN    784
#define NHID   2048
#define NOUT   10
#define NN     2058
#define NE     262144
#define TSTEPS 30
#define NBLK   148
#define NTHR   512
#define WPB    16
#define NCLS   (NHID*10)                 // 20480 classes (src, delay)
#define CPB    ((NCLS + NBLK - 1)/NBLK)  // 139 classes per block
#define CAP    2560                      // smem edge capacity per block

// ---------------- static device state ----------------
__device__ __align__(16) float    d_val[16*NCLS*BATCH];  // masked value ring [slot][cls][b] (84MB)
__device__ __align__(16) float    d_vexc[2][NHID*BATCH]; // double-buffered V_exc [n][b]
__device__ uint32_t d_fired[2][NHID*2];                  // fired bitmaps, double-buffered
__device__ __align__(16) float    d_inp[NHID*BATCH];     // input currents [n][b]
__device__ uint32_t d_hist[NN];
__device__ uint32_t d_off[NN+1];
__device__ uint32_t d_cursor[NN];
__device__ __align__(16) uint2    d_edge[NE];            // CSR by tgt: {cls*64 | dm6<<21, w}
__device__ unsigned g_cnt = 0;
__device__ volatile unsigned g_gen = 0;

// ---------------- zero kernel: d_val ring + hist ----------------
__global__ void zero_kernel() {
    int g = blockIdx.x * blockDim.x + threadIdx.x;
    int st = gridDim.x * blockDim.x;
    float4 z = make_float4(0.f, 0.f, 0.f, 0.f);
    float4* v4 = (float4*)d_val;
    for (int i = g; i < 16*NCLS*BATCH/4; i += st) v4[i] = z;
    for (int i = g; i < NN; i += st) d_hist[i] = 0u;
}

// ---------------- input GEMM: d_inp[n*64+b] = sum_k x[b,k] W[k,n] ----------------
__global__ void gemm_kernel(const float* __restrict__ x, const float* __restrict__ W) {
    __shared__ float sx[4][NIN];
    int n  = blockIdx.x * 256 + threadIdx.x;
    int b0 = blockIdx.y * 4;
    for (int i = threadIdx.x; i < 4*NIN; i += 256) {
        int bb = i / NIN, kk = i - bb * NIN;
        sx[bb][kk] = x[(b0 + bb) * NIN + kk];
    }
    __syncthreads();
    float a0 = 0.f, a1 = 0.f, a2 = 0.f, a3 = 0.f;
#pragma unroll 4
    for (int k = 0; k < NIN; k++) {
        float w = W[k * NHID + n];
        a0 += sx[0][k] * w; a1 += sx[1][k] * w;
        a2 += sx[2][k] * w; a3 += sx[3][k] * w;
    }
    d_inp[n*64 + b0 + 0] = a0;
    d_inp[n*64 + b0 + 1] = a1;
    d_inp[n*64 + b0 + 2] = a2;
    d_inp[n*64 + b0 + 3] = a3;
}

// ---------------- grid barrier ----------------
__device__ __forceinline__ void gridbar() {
    __syncthreads();
    if (threadIdx.x == 0) {
        __threadfence();
        unsigned gen = g_gen;
        if (atomicInc(&g_cnt, NBLK - 1) == NBLK - 1) {
            __threadfence();
            g_gen = gen + 1;
        } else {
            while (g_gen == gen) __nanosleep(32);
        }
        __threadfence();
    }
    __syncthreads();
}

__device__ __forceinline__ uint32_t spread16(uint32_t x) {
    x &= 0xFFFFu;
    x = (x | (x << 8)) & 0x00FF00FFu;
    x = (x | (x << 4)) & 0x0F0F0F0Fu;
    x = (x | (x << 2)) & 0x33333333u;
    x = (x | (x << 1)) & 0x55555555u;
    return x;
}

// ---------------- launch phase (step u): counters + masked-value write ----------------
__device__ __forceinline__ void launch_phase(int u, const uint32_t* __restrict__ s_cmeta,
                                             uint32_t* __restrict__ scnt) {
    int wid = threadIdx.x >> 5, lane = threadIdx.x & 31;
    int sub = lane >> 4, q = lane & 15;
    int buf = u & 1;
    int wslot = u & 15;
#pragma unroll
    for (int k = 0; k < 5; k++) {
        int cl = k * 32 + wid * 2 + sub;
        if (cl >= CPB) break;
        uint32_t cm = s_cmeta[cl];
        if (cm == 0xFFFFFFFFu) continue;
        uint32_t s = cm & 0xFFFFu, d = cm >> 16;
        uint32_t fw = __ldcg(&d_fired[buf][s*2 + (q >> 3)]);
        uint32_t f4 = (fw >> ((q & 7) * 4)) & 15u;
        uint32_t c = scnt[cl*16 + q];
        uint32_t fm = ((f4 * 0x00204081u) & 0x01010101u) * 0xFFu;
        uint32_t lm = __vcmpeq4(c, 0u) & fm;
        scnt[cl*16 + q] = __vsubus4(c, 0x01010101u) | (lm & (d * 0x01010101u));
        uint32_t cg = blockIdx.x * CPB + cl;
        float4 ve = __ldcg((const float4*)&d_vexc[buf][s*64 + q*4]);
        float4 o;
        o.x = (lm & 0x000000FFu) ? ve.x : 0.f;
        o.y = (lm & 0x0000FF00u) ? ve.y : 0.f;
        o.z = (lm & 0x00FF0000u) ? ve.z : 0.f;
        o.w = (lm & 0xFF000000u) ? ve.w : 0.f;
        *(float4*)&d_val[(unsigned)wslot * (NCLS*64) + cg*64 + q*4] = o;
    }
}

// ---------------- consumer body ----------------
#define EDGE_BODY(ED)                                                          \
    {                                                                          \
        uint32_t cx = (ED).x;                                                  \
        uint32_t off = cx & 0x1FFFFFu;             /* cls*64 */                \
        uint32_t dm6 = cx >> 21;                                               \
        uint32_t slot = (uu - dm6) & 15u;                                      \
        float w = __uint_as_float((ED).y);                                     \
        float2 v = __ldcg((const float2*)(valbase + slot * (NCLS*64) + off));  \
        I0 += w * v.x;                                                         \
        I1 += w * v.y;                                                         \
    }

// ---------------- neuron + delivery (step u): warp owns target n ----------------
__device__ __forceinline__ void neuron_phase(int u, int n, int beg, int end, int rbeg,
        bool fits, const uint2* __restrict__ s_edge,
        float& vm0, float& vm1, float& acc0, float& acc1) {
    if (n >= NN) return;
    int lane = threadIdx.x & 31;
    float I0 = 0.f, I1 = 0.f;
    const float* valbase = d_val + 2*lane;
    uint32_t uu = (unsigned)u - 6u;
    int cnt = end - beg;
    if (fits) {
#pragma unroll 8
        for (int i = 0; i < cnt; i++) { uint2 ed = s_edge[rbeg + i]; EDGE_BODY(ed) }
    } else {
#pragma unroll 8
        for (int i = 0; i < cnt; i++) { uint2 ed = __ldg(&d_edge[beg + i]); EDGE_BODY(ed) }
    }
    bool hid = n < NHID;
    if (hid && (u % 3) == 2) {
        float2 ip = *(const float2*)&d_inp[n*64 + 2*lane];
        I0 += ip.x; I1 += ip.y;
    }
    vm0 += (I0 - vm0) * 0.1f;
    vm1 += (I1 - vm1) * 0.1f;
    if (!hid) { acc0 += vm0; acc1 += vm1; return; }
    float ve0 = fmaxf(0.f, vm0 - 0.25f);
    float ve1 = fmaxf(0.f, vm1 - 0.25f);
    bool f0 = ve0 > 0.f, f1 = ve1 > 0.f;
    if (f0) vm0 = -0.2f;
    if (f1) vm1 = -0.2f;
    int buf = u & 1;
    *(float2*)&d_vexc[buf][n*64 + 2*lane] = make_float2(ve0, ve1);
    uint32_t b0 = __ballot_sync(0xffffffffu, f0);
    uint32_t b1 = __ballot_sync(0xffffffffu, f1);
    uint32_t w0 = spread16(b0 & 0xFFFFu) | (spread16(b1 & 0xFFFFu) << 1);
    uint32_t w1 = spread16(b0 >> 16)     | (spread16(b1 >> 16) << 1);
    if (lane == 0) d_fired[buf][n*2]     = w0;
    if (lane == 1) d_fired[buf][n*2 + 1] = w1;
}

// ---------------- persistent simulation kernel ----------------
__global__ void __launch_bounds__(NTHR, 1) sim_kernel(
        const float* __restrict__ We, const float* __restrict__ Le,
        const int* __restrict__ src, const int* __restrict__ tgt,
        float* __restrict__ out) {
    __shared__ uint2    s_edge[CAP];       // also reused as scan scratch (>=2*NN u32)
    __shared__ uint32_t scnt[CPB*16];
    __shared__ uint32_t s_cmeta[CPB];
    int tid = threadIdx.x;
    int bid = blockIdx.x;
    int gtid = bid * NTHR + tid;

    for (int i = tid; i < CPB*16; i += NTHR) scnt[i] = 0u;
    for (int i = tid; i < CPB; i += NTHR) {
        uint32_t cg = bid * CPB + i;
        s_cmeta[i] = (cg < NCLS) ? ((cg / 10u) | (((cg % 10u) + 6u) << 16)) : 0xFFFFFFFFu;
    }

    // ---- 1. histogram over targets ----
    for (int e = gtid; e < NE; e += NBLK*NTHR)
        atomicAdd(&d_hist[tgt[e]], 1u);
    gridbar();

    // ---- 2. scan (block 0 only), scratch = s_edge storage ----
    if (bid == 0) {
        uint32_t* sa = (uint32_t*)s_edge;
        uint32_t* sb = sa + NN;
        for (int i = tid; i < NN; i += NTHR) sa[i] = d_hist[i];
        __syncthreads();
        uint32_t *pin = sa, *pout = sb;
        for (int off = 1; off < NN; off <<= 1) {
            for (int i = tid; i < NN; i += NTHR)
                pout[i] = pin[i] + (i >= off ? pin[i - off] : 0u);
            __syncthreads();
            uint32_t* t = pin; pin = pout; pout = t;
        }
        for (int i = tid; i < NN; i += NTHR) {
            d_off[i+1]  = pin[i];
            d_cursor[i] = (i > 0) ? pin[i-1] : 0u;
        }
        if (tid == 0) d_off[0] = 0u;
    }
    gridbar();

    // ---- 3. scatter into CSR ----
    for (int e = gtid; e < NE; e += NBLK*NTHR) {
        uint32_t dm6 = (uint32_t)(int)(Le[e] * 2.0f + 0.5f) - 6u;   // 0..9
        uint32_t s = (uint32_t)src[e];
        uint32_t pos = atomicAdd(&d_cursor[tgt[e]], 1u);
        d_edge[pos] = make_uint2((s*10u + dm6)*64u | (dm6 << 21), __float_as_uint(We[e]));
    }
    gridbar();

    // ---- 4. copy this block's CSR segment to smem ----
    int n0 = bid * WPB;
    int blockBeg = 0; bool fits = false; int total = 0;
    if (n0 < NN) {
        int nEnd = n0 + WPB; if (nEnd > NN) nEnd = NN;
        blockBeg = d_off[n0];
        total = d_off[nEnd] - blockBeg;
        fits = (total <= CAP);
        if (fits)
            for (int i = tid; i < total; i += NTHR)
                s_edge[i] = __ldg(&d_edge[blockBeg + i]);
    }
    __syncthreads();

    int n = n0 + (tid >> 5);
    int beg = 0, end = 0, rbeg = 0;
    if (n < NN) { beg = d_off[n]; end = d_off[n+1]; rbeg = beg - blockBeg; }
    float vm0 = 0.f, vm1 = 0.f, acc0 = 0.f, acc1 = 0.f;

    neuron_phase(0, n, beg, end, rbeg, fits, s_edge, vm0, vm1, acc0, acc1);
    gridbar();
    for (int u = 0; u < TSTEPS; u++) {
        launch_phase(u, s_cmeta, scnt);
        if (u + 1 < TSTEPS)
            neuron_phase(u + 1, n, beg, end, rbeg, fits, s_edge, vm0, vm1, acc0, acc1);
        gridbar();
    }
    if (n >= NHID && n < NN) {
        int lane = tid & 31;
        int o = n - NHID;
        out[(2*lane)   * NOUT + o] = acc0 * (1.0f / (float)TSTEPS);
        out[(2*lane+1) * NOUT + o] = acc1 * (1.0f / (float)TSTEPS);
    }
}

extern "C" void kernel_launch(void* const* d_in, const int* in_sizes, int n_in,
                              void* d_out, int out_size) {
    const float* x   = (const float*)d_in[0];
    const float* W   = (const float*)d_in[1];
    const float* We  = (const float*)d_in[2];
    const float* Le  = (const float*)d_in[3];
    const int*   src = (const int*)d_in[4];
    const int*   tgt = (const int*)d_in[5];
    float* out = (float*)d_out;
    (void)in_sizes; (void)n_in; (void)out_size;

    zero_kernel<<<4096, 256>>>();
    dim3 gg(8, 16);
    gemm_kernel<<<gg, 256>>>(x, W);
    sim_kernel<<<NBLK, NTHR>>>(We, Le, src, tgt, out);
}

// round 9
// speedup vs baseline: 4.3196x; 1.0221x over previous
#include <cuda_runtime.h>
#include <stdint.h>

#define BATCH  64
#define NIN    784
#define NHID   2048
#define NOUT   10
#define NN     2058
#define NE     262144
#define TSTEPS 30
#define NBLK   148
#define NTHR   512
#define WPB    16
#define NCLS   (NHID*10)                 // 20480 classes (src, delay)
#define CPB    ((NCLS + NBLK - 1)/NBLK)  // 139 classes per block
#define CAP    2560                      // smem edge capacity per block

// dynamic smem layout
#define SM_EDGE_B (CAP*8)                // 20480
#define SM_ACT_B  (NCLS)                 // 20480
#define SM_CNT_B  (CPB*16*4)             // 8896
#define SM_CM_B   (CPB*4)                // 556 -> pad 576
#define SMEM_B    (SM_EDGE_B + SM_ACT_B + SM_CNT_B + 576)

// ---------------- static device state ----------------
__device__ __align__(16) float    d_val[16*NCLS*BATCH];  // value ring [slot][cls][b] (84MB, act-gated, never zeroed)
__device__ __align__(16) uint8_t  d_actd[16*NCLS];       // activity ring, DELIVERY-step indexed
__device__ __align__(16) float    d_vexc[2][NHID*BATCH]; // double-buffered V_exc [n][b]
__device__ uint32_t d_fired[2][NHID*2];                  // fired bitmaps, double-buffered
__device__ __align__(16) float    d_inp[NHID*BATCH];     // input currents [n][b]
__device__ uint32_t d_hist[NN];
__device__ uint32_t d_off[NN+1];
__device__ uint32_t d_cursor[NN];
__device__ __align__(16) uint2    d_edge[NE];            // CSR by tgt: {cls | dm6<<21, w}
__device__ uint32_t d_flags[NBLK];                       // barrier generation flags

// ---------------- input GEMM: d_inp[n*64+b] = sum_k x[b,k] W[k,n] ----------------
__global__ void gemm_kernel(const float* __restrict__ x, const float* __restrict__ W) {
    __shared__ float sx[4][NIN];
    int n  = blockIdx.x * 256 + threadIdx.x;
    int b0 = blockIdx.y * 4;
    for (int i = threadIdx.x; i < 4*NIN; i += 256) {
        int bb = i / NIN, kk = i - bb * NIN;
        sx[bb][kk] = x[(b0 + bb) * NIN + kk];
    }
    __syncthreads();
    float a0 = 0.f, a1 = 0.f, a2 = 0.f, a3 = 0.f;
#pragma unroll 4
    for (int k = 0; k < NIN; k++) {
        float w = W[k * NHID + n];
        a0 += sx[0][k] * w; a1 += sx[1][k] * w;
        a2 += sx[2][k] * w; a3 += sx[3][k] * w;
    }
    d_inp[n*64 + b0 + 0] = a0;
    d_inp[n*64 + b0 + 1] = a1;
    d_inp[n*64 + b0 + 2] = a2;
    d_inp[n*64 + b0 + 3] = a3;
}

// ---------------- distributed flag grid barrier ----------------
__device__ __forceinline__ void gridbar(uint32_t gen) {
    __syncthreads();
    if (threadIdx.x < 32) {
        __threadfence();
        if (threadIdx.x == 0) __stcg(&d_flags[blockIdx.x], gen);
        bool done = false;
        while (!done) {
            uint32_t mn = 0xFFFFFFFFu;
#pragma unroll
            for (int k = 0; k < 5; k++) {
                int i = threadIdx.x + k * 32;
                uint32_t v = (i < NBLK) ? __ldcg(&d_flags[i]) : 0xFFFFFFFFu;
                mn = min(mn, v);
            }
            done = __all_sync(0xffffffffu, mn >= gen);
            if (!done) __nanosleep(64);
        }
        __threadfence();
    }
    __syncthreads();
}

__device__ __forceinline__ uint32_t spread16(uint32_t x) {
    x &= 0xFFFFu;
    x = (x | (x << 8)) & 0x00FF00FFu;
    x = (x | (x << 4)) & 0x0F0F0F0Fu;
    x = (x | (x << 2)) & 0x33333333u;
    x = (x | (x << 1)) & 0x55555555u;
    return x;
}

// ---------------- launch phase (step u) ----------------
__device__ __forceinline__ void launch_phase(int u, const uint32_t* __restrict__ s_cmeta,
                                             uint32_t* __restrict__ scnt) {
    int wid = threadIdx.x >> 5, lane = threadIdx.x & 31;
    int sub = lane >> 4, q = lane & 15;
    int buf = u & 1;
    int wslot = u & 15;
#pragma unroll
    for (int k = 0; k < 5; k++) {
        int cl = k * 32 + wid * 2 + sub;
        int cli = cl < CPB ? cl : CPB - 1;
        uint32_t cm = s_cmeta[cli];
        bool valid = (cl < CPB) && (cm != 0xFFFFFFFFu);
        uint32_t s = cm & 0xFFFFu, d = cm >> 16;
        uint32_t lm = 0u;
        if (valid) {
            uint32_t fw = __ldcg(&d_fired[buf][s*2 + (q >> 3)]);
            uint32_t f4 = (fw >> ((q & 7) * 4)) & 15u;
            uint32_t c = scnt[cli*16 + q];
            uint32_t fm = ((f4 * 0x00204081u) & 0x01010101u) * 0xFFu;
            lm = __vcmpeq4(c, 0u) & fm;
            scnt[cli*16 + q] = __vsubus4(c, 0x01010101u) | (lm & (d * 0x01010101u));
        }
        uint32_t bal = __ballot_sync(0xffffffffu, lm != 0u);
        uint32_t halfact = (lane < 16) ? (bal & 0xFFFFu) : (bal >> 16);
        uint32_t cg = blockIdx.x * CPB + cl;
        if (valid && q == 0)
            d_actd[(((unsigned)u + d) & 15u) * NCLS + cg] = halfact ? 1u : 0u;
        if (valid && halfact) {
            float4 ve = make_float4(0.f, 0.f, 0.f, 0.f);
            if (lm) ve = __ldcg((const float4*)&d_vexc[buf][s*64 + q*4]);
            float4 o;
            o.x = (lm & 0x000000FFu) ? ve.x : 0.f;
            o.y = (lm & 0x0000FF00u) ? ve.y : 0.f;
            o.z = (lm & 0x00FF0000u) ? ve.z : 0.f;
            o.w = (lm & 0xFF000000u) ? ve.w : 0.f;
            *(float4*)&d_val[(unsigned)wslot * (NCLS*64) + cg*64 + q*4] = o;
        }
    }
}

// ---------------- consumer body ----------------
#define EDGE_BODY(ED)                                                            \
    {                                                                            \
        uint32_t cls = (ED).x & 0x7FFFu;                                         \
        if (s_act[cls]) {                                                        \
            uint32_t dm6 = (ED).x >> 21;                                         \
            uint32_t slot = (uu - dm6) & 15u;                                    \
            float w = __uint_as_float((ED).y);                                   \
            float2 v = __ldcg((const float2*)(valbase + slot*(NCLS*64) + cls*64)); \
            I0 += w * v.x;                                                       \
            I1 += w * v.y;                                                       \
        }                                                                        \
    }

// ---------------- neuron + delivery (step u): warp owns target n ----------------
__device__ __forceinline__ void neuron_phase(int u, int n, int beg, int end, int rbeg,
        bool fits, const uint2* __restrict__ s_edge, const uint8_t* __restrict__ s_act,
        float& vm0, float& vm1, float& acc0, float& acc1) {
    if (n >= NN) return;
    int lane = threadIdx.x & 31;
    float I0 = 0.f, I1 = 0.f;
    const float* valbase = d_val + 2*lane;
    uint32_t uu = (unsigned)u - 6u;
    int cnt = end - beg;
    if (fits) {
#pragma unroll 8
        for (int i = 0; i < cnt; i++) { uint2 ed = s_edge[rbeg + i]; EDGE_BODY(ed) }
    } else {
#pragma unroll 8
        for (int i = 0; i < cnt; i++) { uint2 ed = __ldg(&d_edge[beg + i]); EDGE_BODY(ed) }
    }
    bool hid = n < NHID;
    if (hid && (u % 3) == 2) {
        float2 ip = *(const float2*)&d_inp[n*64 + 2*lane];
        I0 += ip.x; I1 += ip.y;
    }
    vm0 += (I0 - vm0) * 0.1f;
    vm1 += (I1 - vm1) * 0.1f;
    if (!hid) { acc0 += vm0; acc1 += vm1; return; }
    float ve0 = fmaxf(0.f, vm0 - 0.25f);
    float ve1 = fmaxf(0.f, vm1 - 0.25f);
    bool f0 = ve0 > 0.f, f1 = ve1 > 0.f;
    if (f0) vm0 = -0.2f;
    if (f1) vm1 = -0.2f;
    int buf = u & 1;
    *(float2*)&d_vexc[buf][n*64 + 2*lane] = make_float2(ve0, ve1);
    uint32_t b0 = __ballot_sync(0xffffffffu, f0);
    uint32_t b1 = __ballot_sync(0xffffffffu, f1);
    uint32_t w0 = spread16(b0 & 0xFFFFu) | (spread16(b1 & 0xFFFFu) << 1);
    uint32_t w1 = spread16(b0 >> 16)     | (spread16(b1 >> 16) << 1);
    if (lane == 0) d_fired[buf][n*2]     = w0;
    if (lane == 1) d_fired[buf][n*2 + 1] = w1;
}

// ---------------- persistent simulation kernel ----------------
__global__ void __launch_bounds__(NTHR, 1) sim_kernel(
        const float* __restrict__ We, const float* __restrict__ Le,
        const int* __restrict__ src, const int* __restrict__ tgt,
        float* __restrict__ out) {
    extern __shared__ uint8_t smem[];
    uint2*    s_edge  = (uint2*)smem;
    uint8_t*  s_act   = smem + SM_EDGE_B;
    uint32_t* scnt    = (uint32_t*)(smem + SM_EDGE_B + SM_ACT_B);
    uint32_t* s_cmeta = (uint32_t*)(smem + SM_EDGE_B + SM_ACT_B + SM_CNT_B);

    int tid = threadIdx.x;
    int bid = blockIdx.x;
    int gtid = bid * NTHR + tid;
    uint32_t base = __ldcg(&d_flags[bid]);   // all blocks agree (last gen of prev call, or 0)

    for (int i = tid; i < CPB*16; i += NTHR) scnt[i] = 0u;
    for (int i = tid; i < CPB; i += NTHR) {
        uint32_t cg = bid * CPB + i;
        s_cmeta[i] = (cg < NCLS) ? ((cg / 10u) | (((cg % 10u) + 6u) << 16)) : 0xFFFFFFFFu;
    }

    // ---- 0. zero act ring + hist ----
    {
        uint32_t* a4 = (uint32_t*)d_actd;
        for (int i = gtid; i < 16*NCLS/4; i += NBLK*NTHR) a4[i] = 0u;
        for (int i = gtid; i < NN; i += NBLK*NTHR) d_hist[i] = 0u;
    }
    gridbar(base + 1);

    // ---- 1. histogram over targets ----
    for (int e = gtid; e < NE; e += NBLK*NTHR)
        atomicAdd(&d_hist[tgt[e]], 1u);
    gridbar(base + 2);

    // ---- 2. scan (block 0 only), scratch = s_edge storage ----
    if (bid == 0) {
        uint32_t* sa = (uint32_t*)s_edge;
        uint32_t* sb = sa + NN;
        for (int i = tid; i < NN; i += NTHR) sa[i] = d_hist[i];
        __syncthreads();
        uint32_t *pin = sa, *pout = sb;
        for (int off = 1; off < NN; off <<= 1) {
            for (int i = tid; i < NN; i += NTHR)
                pout[i] = pin[i] + (i >= off ? pin[i - off] : 0u);
            __syncthreads();
            uint32_t* t = pin; pin = pout; pout = t;
        }
        for (int i = tid; i < NN; i += NTHR) {
            d_off[i+1]  = pin[i];
            d_cursor[i] = (i > 0) ? pin[i-1] : 0u;
        }
        if (tid == 0) d_off[0] = 0u;
        __syncthreads();
    }
    gridbar(base + 3);

    // ---- 3. scatter into CSR ----
    for (int e = gtid; e < NE; e += NBLK*NTHR) {
        uint32_t dm6 = (uint32_t)(int)(Le[e] * 2.0f + 0.5f) - 6u;   // 0..9
        uint32_t s = (uint32_t)src[e];
        uint32_t pos = atomicAdd(&d_cursor[tgt[e]], 1u);
        d_edge[pos] = make_uint2((s*10u + dm6) | (dm6 << 21), __float_as_uint(We[e]));
    }
    gridbar(base + 4);

    // ---- 4. copy this block's CSR segment to smem ----
    int n0 = bid * WPB;
    int blockBeg = 0; bool fits = false; int total = 0;
    if (n0 < NN) {
        int nEnd = n0 + WPB; if (nEnd > NN) nEnd = NN;
        blockBeg = d_off[n0];
        total = d_off[nEnd] - blockBeg;
        fits = (total <= CAP);
        if (fits)
            for (int i = tid; i < total; i += NTHR)
                s_edge[i] = __ldg(&d_edge[blockBeg + i]);
    }
    // stage act row for step 0 (all zeros, but keeps the pattern uniform)
    {
        uint4* dst = (uint4*)s_act;
        const uint4* srcp = (const uint4*)&d_actd[0];
        for (int i = tid; i < NCLS/16; i += NTHR) dst[i] = __ldcg(&srcp[i]);
    }
    __syncthreads();

    int n = n0 + (tid >> 5);
    int beg = 0, end = 0, rbeg = 0;
    if (n < NN) { beg = d_off[n]; end = d_off[n+1]; rbeg = beg - blockBeg; }
    float vm0 = 0.f, vm1 = 0.f, acc0 = 0.f, acc1 = 0.f;

    neuron_phase(0, n, beg, end, rbeg, fits, s_edge, s_act, vm0, vm1, acc0, acc1);
    gridbar(base + 5);
    for (int u = 0; u < TSTEPS; u++) {
        // stage act row for step u+1 (row (u+1)&15; no conflict with launch(u) writes)
        if (u + 1 < TSTEPS) {
            uint4* dst = (uint4*)s_act;
            const uint4* srcp = (const uint4*)&d_actd[((u+1) & 15) * NCLS];
            for (int i = tid; i < NCLS/16; i += NTHR) dst[i] = __ldcg(&srcp[i]);
        }
        __syncthreads();
        launch_phase(u, s_cmeta, scnt);
        if (u + 1 < TSTEPS)
            neuron_phase(u + 1, n, beg, end, rbeg, fits, s_edge, s_act, vm0, vm1, acc0, acc1);
        gridbar(base + 6 + u);
    }
    if (n >= NHID && n < NN) {
        int lane = tid & 31;
        int o = n - NHID;
        out[(2*lane)   * NOUT + o] = acc0 * (1.0f / (float)TSTEPS);
        out[(2*lane+1) * NOUT + o] = acc1 * (1.0f / (float)TSTEPS);
    }
}

extern "C" void kernel_launch(void* const* d_in, const int* in_sizes, int n_in,
                              void* d_out, int out_size) {
    const float* x   = (const float*)d_in[0];
    const float* W   = (const float*)d_in[1];
    const float* We  = (const float*)d_in[2];
    const float* Le  = (const float*)d_in[3];
    const int*   src = (const int*)d_in[4];
    const int*   tgt = (const int*)d_in[5];
    float* out = (float*)d_out;
    (void)in_sizes; (void)n_in; (void)out_size;

    cudaFuncSetAttribute(sim_kernel, cudaFuncAttributeMaxDynamicSharedMemorySize, SMEM_B);
    dim3 gg(8, 16);
    gemm_kernel<<<gg, 256>>>(x, W);
    sim_kernel<<<NBLK, NTHR, SMEM_B>>>(We, Le, src, tgt, out);
}

// round 10
// speedup vs baseline: 4.5901x; 1.0626x over previous
#include <cuda_runtime.h>
#include <stdint.h>

#define BATCH  64
#define NIN    784
#define NHID   2048
#define NOUT   10
#define NN     2058
#define NE     262144
#define TSTEPS 30
#define NBLK   148
#define NTHR   1024
#define WPB    16                        // neurons per block (one warp PAIR each)
#define NCLS   (NHID*10)                 // 20480 classes (src, delay)
#define CPB    ((NCLS + NBLK - 1)/NBLK)  // 139 classes per block
#define CAP    2560                      // smem edge capacity per block

// dynamic smem layout
#define SM_EDGE_B (CAP*8)                // 20480
#define SM_ACT_B  (NCLS)                 // 20480
#define SM_CNT_B  (CPB*16*4)             // 8896
#define SM_PART_B (WPB*32*8)             // 4096
#define SM_CM_B   576
#define SMEM_B    (SM_EDGE_B + SM_ACT_B + SM_CNT_B + SM_PART_B + SM_CM_B)

// ---------------- static device state ----------------
__device__ __align__(16) float    d_val[16*NCLS*BATCH];  // value ring [slot][cls][b]
__device__ __align__(16) uint8_t  d_actd[16*NCLS];       // activity ring, delivery-step indexed
__device__ __align__(16) float    d_vexc[2][NHID*BATCH];
__device__ uint32_t d_fired[2][NHID*2];
__device__ __align__(16) float    d_inp[NHID*BATCH];
__device__ uint32_t d_hist[NN];
__device__ uint32_t d_off[NN+1];
__device__ uint32_t d_cursor[NN];
__device__ __align__(16) uint2    d_edge[NE];            // CSR by tgt: {cls | dm6<<21, w}
__device__ uint32_t d_flags[NBLK];

// ---------------- input GEMM ----------------
__global__ void gemm_kernel(const float* __restrict__ x, const float* __restrict__ W) {
    __shared__ float sx[4][NIN];
    int n  = blockIdx.x * 256 + threadIdx.x;
    int b0 = blockIdx.y * 4;
    for (int i = threadIdx.x; i < 4*NIN; i += 256) {
        int bb = i / NIN, kk = i - bb * NIN;
        sx[bb][kk] = x[(b0 + bb) * NIN + kk];
    }
    __syncthreads();
    float a0 = 0.f, a1 = 0.f, a2 = 0.f, a3 = 0.f;
#pragma unroll 4
    for (int k = 0; k < NIN; k++) {
        float w = W[k * NHID + n];
        a0 += sx[0][k] * w; a1 += sx[1][k] * w;
        a2 += sx[2][k] * w; a3 += sx[3][k] * w;
    }
    d_inp[n*64 + b0 + 0] = a0;
    d_inp[n*64 + b0 + 1] = a1;
    d_inp[n*64 + b0 + 2] = a2;
    d_inp[n*64 + b0 + 3] = a3;
}

// ---------------- distributed flag grid barrier ----------------
__device__ __forceinline__ void gridbar(uint32_t gen) {
    __syncthreads();
    if (threadIdx.x < 32) {
        __threadfence();
        if (threadIdx.x == 0) __stcg(&d_flags[blockIdx.x], gen);
        bool done = false;
        while (!done) {
            uint32_t mn = 0xFFFFFFFFu;
#pragma unroll
            for (int k = 0; k < 5; k++) {
                int i = threadIdx.x + k * 32;
                uint32_t v = (i < NBLK) ? __ldcg(&d_flags[i]) : 0xFFFFFFFFu;
                mn = min(mn, v);
            }
            done = __all_sync(0xffffffffu, mn >= gen);
            if (!done) __nanosleep(64);
        }
        __threadfence();
    }
    __syncthreads();
}

__device__ __forceinline__ uint32_t spread16(uint32_t x) {
    x &= 0xFFFFu;
    x = (x | (x << 8)) & 0x00FF00FFu;
    x = (x | (x << 4)) & 0x0F0F0F0Fu;
    x = (x | (x << 2)) & 0x33333333u;
    x = (x | (x << 1)) & 0x55555555u;
    return x;
}

// ---------------- launch phase (step u): 32 warps, 2 classes/warp/iter ----------------
__device__ __forceinline__ void launch_phase(int u, const uint32_t* __restrict__ s_cmeta,
                                             uint32_t* __restrict__ scnt) {
    int wid = threadIdx.x >> 5, lane = threadIdx.x & 31;
    int sub = lane >> 4, q = lane & 15;
    int buf = u & 1;
    int wslot = u & 15;
#pragma unroll
    for (int k = 0; k < 3; k++) {
        int cl = k * 64 + wid * 2 + sub;
        int cli = cl < CPB ? cl : CPB - 1;
        uint32_t cm = s_cmeta[cli];
        bool valid = (cl < CPB) && (cm != 0xFFFFFFFFu);
        uint32_t s = cm & 0xFFFFu, d = cm >> 16;
        uint32_t lm = 0u;
        if (valid) {
            uint32_t fw = __ldcg(&d_fired[buf][s*2 + (q >> 3)]);
            uint32_t f4 = (fw >> ((q & 7) * 4)) & 15u;
            uint32_t c = scnt[cli*16 + q];
            uint32_t fm = ((f4 * 0x00204081u) & 0x01010101u) * 0xFFu;
            lm = __vcmpeq4(c, 0u) & fm;
            scnt[cli*16 + q] = __vsubus4(c, 0x01010101u) | (lm & (d * 0x01010101u));
        }
        uint32_t bal = __ballot_sync(0xffffffffu, lm != 0u);
        uint32_t halfact = (lane < 16) ? (bal & 0xFFFFu) : (bal >> 16);
        uint32_t cg = blockIdx.x * CPB + cl;
        if (valid && q == 0)
            d_actd[(((unsigned)u + d) & 15u) * NCLS + cg] = halfact ? 1u : 0u;
        if (valid && halfact) {
            float4 ve = make_float4(0.f, 0.f, 0.f, 0.f);
            if (lm) ve = __ldcg((const float4*)&d_vexc[buf][s*64 + q*4]);
            float4 o;
            o.x = (lm & 0x000000FFu) ? ve.x : 0.f;
            o.y = (lm & 0x0000FF00u) ? ve.y : 0.f;
            o.z = (lm & 0x00FF0000u) ? ve.z : 0.f;
            o.w = (lm & 0xFF000000u) ? ve.w : 0.f;
            *(float4*)&d_val[(unsigned)wslot * (NCLS*64) + cg*64 + q*4] = o;
        }
    }
}

// ---------------- consumer body ----------------
#define EDGE_BODY(ED)                                                            \
    {                                                                            \
        uint32_t cls = (ED).x & 0x7FFFu;                                         \
        if (s_act[cls]) {                                                        \
            uint32_t dm6 = (ED).x >> 21;                                         \
            uint32_t slot = (uu - dm6) & 15u;                                    \
            float w = __uint_as_float((ED).y);                                   \
            float2 v = __ldcg((const float2*)(valbase + slot*(NCLS*64) + cls*64)); \
            I0 += w * v.x;                                                       \
            I1 += w * v.y;                                                       \
        }                                                                        \
    }

// half-edge-list consumption into partial I0,I1
__device__ __forceinline__ void consume_half(int u, int i0, int i1, int goff,
        bool fits, const uint2* __restrict__ s_edge, const uint8_t* __restrict__ s_act,
        float& I0, float& I1) {
    int lane = threadIdx.x & 31;
    const float* valbase = d_val + 2*lane;
    uint32_t uu = (unsigned)u - 6u;
    if (fits) {
#pragma unroll 8
        for (int i = i0; i < i1; i++) { uint2 ed = s_edge[i]; EDGE_BODY(ed) }
    } else {
#pragma unroll 8
        for (int i = i0; i < i1; i++) { uint2 ed = __ldg(&d_edge[goff + i]); EDGE_BODY(ed) }
    }
}

// ---------------- persistent simulation kernel ----------------
__global__ void __launch_bounds__(NTHR, 1) sim_kernel(
        const float* __restrict__ We, const float* __restrict__ Le,
        const int* __restrict__ src, const int* __restrict__ tgt,
        float* __restrict__ out) {
    extern __shared__ uint8_t smem[];
    uint2*    s_edge  = (uint2*)smem;
    uint8_t*  s_act   = smem + SM_EDGE_B;
    uint32_t* scnt    = (uint32_t*)(smem + SM_EDGE_B + SM_ACT_B);
    float2*   s_part  = (float2*)(smem + SM_EDGE_B + SM_ACT_B + SM_CNT_B);
    uint32_t* s_cmeta = (uint32_t*)(smem + SM_EDGE_B + SM_ACT_B + SM_CNT_B + SM_PART_B);

    int tid = threadIdx.x;
    int bid = blockIdx.x;
    int gtid = bid * NTHR + tid;
    uint32_t base = __ldcg(&d_flags[bid]);

    for (int i = tid; i < CPB*16; i += NTHR) scnt[i] = 0u;
    for (int i = tid; i < CPB; i += NTHR) {
        uint32_t cg = bid * CPB + i;
        s_cmeta[i] = (cg < NCLS) ? ((cg / 10u) | (((cg % 10u) + 6u) << 16)) : 0xFFFFFFFFu;
    }

    // ---- 0. zero act ring + hist ----
    {
        uint32_t* a4 = (uint32_t*)d_actd;
        for (int i = gtid; i < 16*NCLS/4; i += NBLK*NTHR) a4[i] = 0u;
        for (int i = gtid; i < NN; i += NBLK*NTHR) d_hist[i] = 0u;
    }
    gridbar(base + 1);

    // ---- 1. histogram over targets ----
    for (int e = gtid; e < NE; e += NBLK*NTHR)
        atomicAdd(&d_hist[tgt[e]], 1u);
    gridbar(base + 2);

    // ---- 2. scan (block 0 only) ----
    if (bid == 0) {
        uint32_t* sa = (uint32_t*)s_edge;
        uint32_t* sb = sa + NN;
        for (int i = tid; i < NN; i += NTHR) sa[i] = d_hist[i];
        __syncthreads();
        uint32_t *pin = sa, *pout = sb;
        for (int off = 1; off < NN; off <<= 1) {
            for (int i = tid; i < NN; i += NTHR)
                pout[i] = pin[i] + (i >= off ? pin[i - off] : 0u);
            __syncthreads();
            uint32_t* t = pin; pin = pout; pout = t;
        }
        for (int i = tid; i < NN; i += NTHR) {
            d_off[i+1]  = pin[i];
            d_cursor[i] = (i > 0) ? pin[i-1] : 0u;
        }
        if (tid == 0) d_off[0] = 0u;
        __syncthreads();
    }
    gridbar(base + 3);

    // ---- 3. scatter into CSR ----
    for (int e = gtid; e < NE; e += NBLK*NTHR) {
        uint32_t dm6 = (uint32_t)(int)(Le[e] * 2.0f + 0.5f) - 6u;   // 0..9
        uint32_t s = (uint32_t)src[e];
        uint32_t pos = atomicAdd(&d_cursor[tgt[e]], 1u);
        d_edge[pos] = make_uint2((s*10u + dm6) | (dm6 << 21), __float_as_uint(We[e]));
    }
    gridbar(base + 4);

    // ---- 4. stage this block's CSR segment ----
    int n0 = bid * WPB;
    int blockBeg = 0; bool fits = false; int total = 0;
    if (n0 < NN) {
        int nEnd = n0 + WPB; if (nEnd > NN) nEnd = NN;
        blockBeg = d_off[n0];
        total = d_off[nEnd] - blockBeg;
        fits = (total <= CAP);
        if (fits)
            for (int i = tid; i < total; i += NTHR)
                s_edge[i] = __ldg(&d_edge[blockBeg + i]);
    }
    {
        uint4* dst = (uint4*)s_act;
        const uint4* srcp = (const uint4*)&d_actd[0];
        for (int i = tid; i < NCLS/16; i += NTHR) dst[i] = __ldcg(&srcp[i]);
    }
    __syncthreads();

    int wid = tid >> 5, lane = tid & 31;
    int pair = wid >> 1, half = wid & 1;
    int n = n0 + pair;
    bool nvalid = (n < NN);
    int cnt = 0, lbeg = 0, goff = 0;
    if (nvalid) {
        int beg = d_off[n], end = d_off[n+1];
        cnt = end - beg;
        lbeg = beg - blockBeg;          // smem-relative start
        goff = beg;                     // global start
    }
    int h0 = cnt >> 1;
    // this warp's half-range (relative indices within neuron's list)
    int i0 = half ? h0 : 0;
    int i1 = half ? cnt : h0;

    float vm0 = 0.f, vm1 = 0.f, acc0 = 0.f, acc1 = 0.f;

    // ---- simulation ----
    for (int u = 0; u <= TSTEPS; u++) {
        bool do_neuron = (u < TSTEPS);
        // consume edges for step u (delivery+state update)
        float I0 = 0.f, I1 = 0.f;
        if (do_neuron && nvalid && i1 > i0)
            consume_half(u, fits ? (lbeg + i0) : i0, fits ? (lbeg + i1) : i1,
                         goff, fits, s_edge, s_act, I0, I1);
        if (half == 1 && nvalid) s_part[pair*32 + lane] = make_float2(I0, I1);
        __syncthreads();
        if (do_neuron && nvalid && half == 0) {
            float2 p = s_part[pair*32 + lane];
            I0 += p.x; I1 += p.y;
            bool hid = n < NHID;
            if (hid && (u % 3) == 2) {
                float2 ip = *(const float2*)&d_inp[n*64 + 2*lane];
                I0 += ip.x; I1 += ip.y;
            }
            vm0 += (I0 - vm0) * 0.1f;
            vm1 += (I1 - vm1) * 0.1f;
            if (!hid) { acc0 += vm0; acc1 += vm1; }
            else {
                float ve0 = fmaxf(0.f, vm0 - 0.25f);
                float ve1 = fmaxf(0.f, vm1 - 0.25f);
                bool f0 = ve0 > 0.f, f1 = ve1 > 0.f;
                if (f0) vm0 = -0.2f;
                if (f1) vm1 = -0.2f;
                int buf = u & 1;
                *(float2*)&d_vexc[buf][n*64 + 2*lane] = make_float2(ve0, ve1);
                uint32_t b0 = __ballot_sync(0xffffffffu, f0);
                uint32_t b1 = __ballot_sync(0xffffffffu, f1);
                uint32_t w0 = spread16(b0 & 0xFFFFu) | (spread16(b1 & 0xFFFFu) << 1);
                uint32_t w1 = spread16(b0 >> 16)     | (spread16(b1 >> 16) << 1);
                if (lane == 0) d_fired[buf][n*2]     = w0;
                if (lane == 1) d_fired[buf][n*2 + 1] = w1;
            }
        } else if (half == 0) {
            __ballot_sync(0xffffffffu, false);
            __ballot_sync(0xffffffffu, false);
        }
        gridbar(base + 5 + u);
        if (u < TSTEPS) {
            // stage act row for step u+1, then launch spikes of step u
            uint4* dst = (uint4*)s_act;
            const uint4* srcp = (const uint4*)&d_actd[((u+1) & 15) * NCLS];
            for (int i = tid; i < NCLS/16; i += NTHR) dst[i] = __ldcg(&srcp[i]);
            __syncthreads();
            launch_phase(u, s_cmeta, scnt);
        }
    }
    // Note: loop order above = neuron(u) ; barrier ; [stage act(u+1); launch(u)] ; next
    // launch(u) needs fired(u) -> written by neuron(u) before the barrier. OK.
    // neuron(u+1) needs act row (u+1) staged and launch writes of step <= u: launch(u)
    // writes act rows (u+6..u+15); staging row (u+1) happens in the SAME region but
    // reads rows written at steps <= u-5 -> disjoint from launch(u) writes? row (u+1)
    // mod 16 vs rows (u+6..u+15) mod 16: (u+1) not in that set. Safe. But neuron(u+1)
    // runs in the NEXT region after gridbar, while OTHER blocks may still be in
    // launch(u)?? No: gridbar(base+5+u) separates; launch(u) happens BEFORE that
    // barrier in the next iteration... (see ordering below)

    if (nvalid && half == 0 && n >= NHID) {
        int o = n - NHID;
        out[(2*lane)   * NOUT + o] = acc0 * (1.0f / (float)TSTEPS);
        out[(2*lane+1) * NOUT + o] = acc1 * (1.0f / (float)TSTEPS);
    }
}

extern "C" void kernel_launch(void* const* d_in, const int* in_sizes, int n_in,
                              void* d_out, int out_size) {
    const float* x   = (const float*)d_in[0];
    const float* W   = (const float*)d_in[1];
    const float* We  = (const float*)d_in[2];
    const float* Le  = (const float*)d_in[3];
    const int*   src = (const int*)d_in[4];
    const int*   tgt = (const int*)d_in[5];
    float* out = (float*)d_out;
    (void)in_sizes; (void)n_in; (void)out_size;

    cudaFuncSetAttribute(sim_kernel, cudaFuncAttributeMaxDynamicSharedMemorySize, SMEM_B);
    dim3 gg(8, 16);
    gemm_kernel<<<gg, 256>>>(x, W);
    sim_kernel<<<NBLK, NTHR, SMEM_B>>>(We, Le, src, tgt, out);
}

// round 11
// speedup vs baseline: 5.5568x; 1.2106x over previous
#include <cuda_runtime.h>
#include <stdint.h>

#define BATCH  64
#define NIN    784
#define NHID   2048
#define NOUT   10
#define NN     2058
#define NE     262144
#define TSTEPS 30
#define NBH    128                 // blocks owning hidden neurons+classes
#define NBLK   129                 // + 1 output block
#define NTHR   1024
#define WPB    16                  // neurons per block
#define NCLS   (NHID*10)           // 20480 classes (src, delay)
#define CPB    160                 // classes per hidden block (16 neurons x 10 delays)
#define ROWW   (NCLS/32)           // 640 words per act row
#define NSLOT  32                  // ring depth (covers 6-step region skew)
#define CAP    2560

// dynamic smem layout (bytes)
#define SM_EDGE_B (CAP*8)          // 20480
#define SM_ACT_B  (6*ROWW*4)       // 15360
#define SM_CNT_B  (CPB*16*4)       // 10240
#define SM_PART_B (WPB*32*8)       // 4096
#define SM_VEXC_B (WPB*64*4)       // 4096
#define SM_INP_B  (WPB*64*4)       // 4096
#define SM_FIRE_B (WPB*2*4)        // 128
#define SM_CM_B   (CPB*4)          // 640
#define SMEM_B (SM_EDGE_B+SM_ACT_B+SM_CNT_B+SM_PART_B+SM_VEXC_B+SM_INP_B+SM_FIRE_B+SM_CM_B)

// ---------------- static device state ----------------
__device__ __align__(16) float    d_val[NSLOT*NCLS*BATCH];  // value ring [slot][cls][b] (~168MB, act-gated)
__device__ __align__(16) uint32_t d_actb[NSLOT*ROWW];       // act bitmap ring, delivery-step rows
__device__ __align__(16) float    d_inp[NHID*BATCH];        // input currents [n][b]
__device__ uint32_t d_hist[NN];
__device__ uint32_t d_off[NN+1];
__device__ uint32_t d_cursor[NN];
__device__ __align__(16) uint2    d_edge[NE];               // CSR by tgt: {cls | dm6<<21, w}
__device__ uint32_t d_flags[NBLK];

// ---------------- input GEMM: d_inp[n*64+b] = sum_k x[b,k] W[k,n] ----------------
__global__ void gemm_kernel(const float* __restrict__ x, const float* __restrict__ W) {
    __shared__ float sx[8*NIN];                 // 25KB
    int n  = blockIdx.x * 256 + threadIdx.x;    // blockIdx.x in [0,8)
    int b0 = blockIdx.y * 8;                    // blockIdx.y in [0,8)
    for (int i = threadIdx.x; i < 8*NIN; i += 256) {
        int bb = i / NIN, kk = i - bb * NIN;
        sx[bb*NIN + kk] = x[(b0 + bb) * NIN + kk];
    }
    __syncthreads();
    float a[8];
#pragma unroll
    for (int bb = 0; bb < 8; bb++) a[bb] = 0.f;
#pragma unroll 4
    for (int k = 0; k < NIN; k++) {
        float w = W[k * NHID + n];
#pragma unroll
        for (int bb = 0; bb < 8; bb++) a[bb] += sx[bb*NIN + k] * w;
    }
#pragma unroll
    for (int bb = 0; bb < 8; bb++) d_inp[n*64 + b0 + bb] = a[bb];
}

// ---------------- distributed flag grid barrier ----------------
__device__ __forceinline__ void gridbar(uint32_t gen) {
    __syncthreads();
    if (threadIdx.x < 32) {
        __threadfence();
        if (threadIdx.x == 0) __stcg(&d_flags[blockIdx.x], gen);
        bool done = false;
        while (!done) {
            uint32_t mn = 0xFFFFFFFFu;
#pragma unroll
            for (int k = 0; k < 5; k++) {
                int i = threadIdx.x + k * 32;
                uint32_t v = (i < NBLK) ? __ldcg(&d_flags[i]) : 0xFFFFFFFFu;
                mn = min(mn, v);
            }
            done = __all_sync(0xffffffffu, mn >= gen);
            if (!done) __nanosleep(64);
        }
        __threadfence();
    }
    __syncthreads();
}

__device__ __forceinline__ uint32_t spread16(uint32_t x) {
    x &= 0xFFFFu;
    x = (x | (x << 8)) & 0x00FF00FFu;
    x = (x | (x << 4)) & 0x0F0F0F0Fu;
    x = (x | (x << 2)) & 0x33333333u;
    x = (x | (x << 1)) & 0x55555555u;
    return x;
}

// ---------------- launch phase (step u): classes block-local, fired/vexc in smem ----------------
__device__ __forceinline__ void launch_phase(int u, int bid,
        const uint32_t* __restrict__ s_cmeta, uint32_t* __restrict__ scnt,
        const uint32_t* __restrict__ s_fired, const float* __restrict__ s_vexc) {
    int wid = threadIdx.x >> 5, lane = threadIdx.x & 31;
    int sub = lane >> 4, q = lane & 15;
    int wslot = u & (NSLOT-1);
#pragma unroll
    for (int k = 0; k < 3; k++) {
        int cl = k * 64 + wid * 2 + sub;
        bool valid = (cl < CPB);
        int cli = valid ? cl : 0;
        uint32_t cm = s_cmeta[cli];
        uint32_t nl = cm & 0xFFFFu, d = cm >> 16;     // local neuron, delay 6..15
        uint32_t lm = 0u;
        if (valid) {
            uint32_t fw = s_fired[nl*2 + (q >> 3)];
            uint32_t f4 = (fw >> ((q & 7) * 4)) & 15u;
            uint32_t c = scnt[cli*16 + q];
            uint32_t fm = ((f4 * 0x00204081u) & 0x01010101u) * 0xFFu;
            lm = __vcmpeq4(c, 0u) & fm;
            scnt[cli*16 + q] = __vsubus4(c, 0x01010101u) | (lm & (d * 0x01010101u));
        }
        uint32_t bal = __ballot_sync(0xffffffffu, lm != 0u);
        uint32_t halfact = (lane < 16) ? (bal & 0xFFFFu) : (bal >> 16);
        if (valid && halfact) {
            uint32_t cg = (uint32_t)bid * CPB + cl;
            if (q == 0) {
                int row = (u + (int)d) & (NSLOT-1);
                atomicOr(&d_actb[row*ROWW + (cg >> 5)], 1u << (cg & 31u));
            }
            const float4 ve = *(const float4*)&s_vexc[nl*64 + q*4];
            float4 o;
            o.x = (lm & 0x000000FFu) ? ve.x : 0.f;
            o.y = (lm & 0x0000FF00u) ? ve.y : 0.f;
            o.z = (lm & 0x00FF0000u) ? ve.z : 0.f;
            o.w = (lm & 0xFF000000u) ? ve.w : 0.f;
            *(float4*)&d_val[(unsigned)wslot * (NCLS*64) + cg*64 + q*4] = o;
        }
    }
}

// ---------------- consumer body ----------------
#define EDGE_BODY(ED)                                                            \
    {                                                                            \
        uint32_t cls = (ED).x & 0x7FFFu;                                         \
        if ((actrow[cls >> 5] >> (cls & 31u)) & 1u) {                            \
            uint32_t dm6 = (ED).x >> 21;                                         \
            uint32_t slot = (uu - dm6) & (NSLOT-1u);                             \
            float w = __uint_as_float((ED).y);                                   \
            float2 v = __ldcg((const float2*)(valbase + slot*(NCLS*64) + cls*64)); \
            I0 += w * v.x;                                                       \
            I1 += w * v.y;                                                       \
        }                                                                        \
    }

__device__ __forceinline__ void consume_half(int u, int i0, int i1, int goff,
        bool fits, const uint2* __restrict__ s_edge, const uint32_t* __restrict__ actrow,
        float& I0, float& I1) {
    int lane = threadIdx.x & 31;
    const float* valbase = d_val + 2*lane;
    uint32_t uu = (uint32_t)(u - 6);
    if (fits) {
#pragma unroll 8
        for (int i = i0; i < i1; i++) { uint2 ed = s_edge[i]; EDGE_BODY(ed) }
    } else {
#pragma unroll 8
        for (int i = i0; i < i1; i++) { uint2 ed = __ldg(&d_edge[goff + i]); EDGE_BODY(ed) }
    }
}

// ---------------- persistent simulation kernel ----------------
__global__ void __launch_bounds__(NTHR, 1) sim_kernel(
        const float* __restrict__ We, const float* __restrict__ Le,
        const int* __restrict__ src, const int* __restrict__ tgt,
        float* __restrict__ out) {
    extern __shared__ uint8_t smem[];
    uint2*    s_edge  = (uint2*)smem;
    uint32_t* s_actw  = (uint32_t*)(smem + SM_EDGE_B);
    uint32_t* scnt    = (uint32_t*)(smem + SM_EDGE_B + SM_ACT_B);
    float2*   s_part  = (float2*)(smem + SM_EDGE_B + SM_ACT_B + SM_CNT_B);
    float*    s_vexc  = (float*)(smem + SM_EDGE_B + SM_ACT_B + SM_CNT_B + SM_PART_B);
    float*    s_inp   = (float*)(smem + SM_EDGE_B + SM_ACT_B + SM_CNT_B + SM_PART_B + SM_VEXC_B);
    uint32_t* s_fired = (uint32_t*)(smem + SM_EDGE_B + SM_ACT_B + SM_CNT_B + SM_PART_B + SM_VEXC_B + SM_INP_B);
    uint32_t* s_cmeta = (uint32_t*)(smem + SM_EDGE_B + SM_ACT_B + SM_CNT_B + SM_PART_B + SM_VEXC_B + SM_INP_B + SM_FIRE_B);

    int tid = threadIdx.x;
    int bid = blockIdx.x;
    int gtid = bid * NTHR + tid;
    uint32_t base = __ldcg(&d_flags[bid]);

    for (int i = tid; i < CPB*16; i += NTHR) scnt[i] = 0u;
    if (tid < CPB) s_cmeta[tid] = (uint32_t)(tid / 10) | (((uint32_t)(tid % 10) + 6u) << 16);

    // ---- 0. zero act ring + hist ----
    for (int i = gtid; i < NSLOT*ROWW; i += NBLK*NTHR) d_actb[i] = 0u;
    for (int i = gtid; i < NN; i += NBLK*NTHR) d_hist[i] = 0u;
    gridbar(base + 1);

    // ---- 1. histogram over targets ----
    for (int e = gtid; e < NE; e += NBLK*NTHR)
        atomicAdd(&d_hist[tgt[e]], 1u);
    gridbar(base + 2);

    // ---- 2. scan (block 0), scratch = s_edge ----
    if (bid == 0) {
        uint32_t* sa = (uint32_t*)s_edge;
        uint32_t* sb = sa + NN;
        for (int i = tid; i < NN; i += NTHR) sa[i] = d_hist[i];
        __syncthreads();
        uint32_t *pin = sa, *pout = sb;
        for (int off = 1; off < NN; off <<= 1) {
            for (int i = tid; i < NN; i += NTHR)
                pout[i] = pin[i] + (i >= off ? pin[i - off] : 0u);
            __syncthreads();
            uint32_t* t = pin; pin = pout; pout = t;
        }
        for (int i = tid; i < NN; i += NTHR) {
            d_off[i+1]  = pin[i];
            d_cursor[i] = (i > 0) ? pin[i-1] : 0u;
        }
        if (tid == 0) d_off[0] = 0u;
        __syncthreads();
    }
    gridbar(base + 3);

    // ---- 3. scatter into CSR ----
    for (int e = gtid; e < NE; e += NBLK*NTHR) {
        uint32_t dm6 = (uint32_t)(int)(Le[e] * 2.0f + 0.5f) - 6u;   // 0..9
        uint32_t s = (uint32_t)src[e];
        uint32_t pos = atomicAdd(&d_cursor[tgt[e]], 1u);
        d_edge[pos] = make_uint2((s*10u + dm6) | (dm6 << 21), __float_as_uint(We[e]));
    }
    gridbar(base + 4);

    // ---- 4. stage CSR segment + inp ----
    int n0 = bid * WPB;
    int blockBeg = 0; bool fits = false; int total = 0;
    {
        int nEnd = n0 + WPB; if (nEnd > NN) nEnd = NN;
        blockBeg = d_off[n0];
        total = d_off[nEnd] - blockBeg;
        fits = (total <= CAP);
        if (fits)
            for (int i = tid; i < total; i += NTHR)
                s_edge[i] = __ldg(&d_edge[blockBeg + i]);
    }
    if (bid < NBH) s_inp[tid] = d_inp[n0*64 + tid];   // 16*64 = 1024 = NTHR
    __syncthreads();

    int wid = tid >> 5, lane = tid & 31;
    int pair = wid >> 1, half = wid & 1;
    int n = n0 + pair;
    bool nvalid = (n < NN);
    int cnt = 0, lbeg = 0, goff = 0;
    if (nvalid) {
        int beg = d_off[n], end = d_off[n+1];
        cnt = end - beg;
        lbeg = beg - blockBeg;
        goff = beg;
    }
    int h0 = cnt >> 1;
    int i0 = half ? h0 : 0;
    int i1 = half ? cnt : h0;

    float vm0 = 0.f, vm1 = 0.f, acc0 = 0.f, acc1 = 0.f;

    // ---- simulation: 5 regions x 6 steps, 1 gridbar per region ----
    for (int r = 0; r < 5; r++) {
        int u0 = r * 6;
        gridbar(base + 5 + r);
        // stage act rows u0..u0+5 (all writers pre-barrier)
        for (int i = tid; i < 6*ROWW; i += NTHR) {
            int j = i / ROWW, w = i - j*ROWW;
            s_actw[i] = __ldcg(&d_actb[((u0 + j) & (NSLOT-1))*ROWW + w]);
        }
        // clear own words of rows consumed 2 regions ago (next writers are our own, later)
        if (bid < NBH && tid < 30) {
            int j = tid / 5, w = tid - (tid/5)*5;
            __stcg(&d_actb[((u0 - 12 + j + NSLOT) & (NSLOT-1))*ROWW + bid*5 + w], 0u);
        }
        __syncthreads();

        for (int j = 0; j < 6; j++) {
            int u = u0 + j;
            const uint32_t* actrow = s_actw + j*ROWW;
            float I0 = 0.f, I1 = 0.f;
            if (nvalid && i1 > i0)
                consume_half(u, fits ? (lbeg + i0) : i0, fits ? (lbeg + i1) : i1,
                             goff, fits, s_edge, actrow, I0, I1);
            if (half == 1 && nvalid) s_part[pair*32 + lane] = make_float2(I0, I1);
            __syncthreads();
            if (nvalid && half == 0) {
                float2 p = s_part[pair*32 + lane];
                I0 += p.x; I1 += p.y;
                bool hid = n < NHID;
                if (hid && (u % 3) == 2) {
                    float2 ip = *(const float2*)&s_inp[pair*64 + 2*lane];
                    I0 += ip.x; I1 += ip.y;
                }
                vm0 += (I0 - vm0) * 0.1f;
                vm1 += (I1 - vm1) * 0.1f;
                if (!hid) { acc0 += vm0; acc1 += vm1; }
                else {
                    float ve0 = fmaxf(0.f, vm0 - 0.25f);
                    float ve1 = fmaxf(0.f, vm1 - 0.25f);
                    bool f0 = ve0 > 0.f, f1 = ve1 > 0.f;
                    if (f0) vm0 = -0.2f;
                    if (f1) vm1 = -0.2f;
                    *(float2*)&s_vexc[pair*64 + 2*lane] = make_float2(ve0, ve1);
                    uint32_t b0 = __ballot_sync(0xffffffffu, f0);
                    uint32_t b1 = __ballot_sync(0xffffffffu, f1);
                    uint32_t w0 = spread16(b0 & 0xFFFFu) | (spread16(b1 & 0xFFFFu) << 1);
                    uint32_t w1 = spread16(b0 >> 16)     | (spread16(b1 >> 16) << 1);
                    if (lane == 0) s_fired[pair*2]     = w0;
                    if (lane == 1) s_fired[pair*2 + 1] = w1;
                }
            } else if (half == 0) {
                __ballot_sync(0xffffffffu, false);
                __ballot_sync(0xffffffffu, false);
            }
            __syncthreads();                    // s_fired/s_vexc ready
            if (bid < NBH) launch_phase(u, bid, s_cmeta, scnt, s_fired, s_vexc);
            __syncthreads();                    // launch done before next step's s_fired write
        }
    }

    if (nvalid && half == 0 && n >= NHID) {
        int o = n - NHID;
        out[(2*lane)   * NOUT + o] = acc0 * (1.0f / (float)TSTEPS);
        out[(2*lane+1) * NOUT + o] = acc1 * (1.0f / (float)TSTEPS);
    }
}

extern "C" void kernel_launch(void* const* d_in, const int* in_sizes, int n_in,
                              void* d_out, int out_size) {
    const float* x   = (const float*)d_in[0];
    const float* W   = (const float*)d_in[1];
    const float* We  = (const float*)d_in[2];
    const float* Le  = (const float*)d_in[3];
    const int*   src = (const int*)d_in[4];
    const int*   tgt = (const int*)d_in[5];
    float* out = (float*)d_out;
    (void)in_sizes; (void)n_in; (void)out_size;

    cudaFuncSetAttribute(sim_kernel, cudaFuncAttributeMaxDynamicSharedMemorySize, SMEM_B);
    dim3 gg(8, 8);
    gemm_kernel<<<gg, 256>>>(x, W);
    sim_kernel<<<NBLK, NTHR, SMEM_B>>>(We, Le, src, tgt, out);
}

// round 12
// speedup vs baseline: 6.5721x; 1.1827x over previous
#include <cuda_runtime.h>
#include <stdint.h>

#define BATCH  64
#define NIN    784
#define NHID   2048
#define NOUT   10
#define NN     2058
#define NE     262144
#define TSTEPS 30
#define NBH    128                 // blocks owning hidden neurons+classes
#define NBLK   129                 // + 1 output block
#define NTHR   1024
#define WPB    16                  // neurons per block
#define NCLS   (NHID*10)           // 20480 classes (src, delay)
#define CPB    160                 // classes per hidden block
#define ROWW   (NCLS/32)           // 640 words per act row
#define NSLOT  32                  // ring depth
#define CAP    2560

// dynamic smem layout (bytes)
#define SM_EDGE_B (CAP*8)          // 20480
#define SM_ACT_B  (6*ROWW*4)       // 15360
#define SM_CNT_B  (CPB*16*4)       // 10240
#define SM_PART_B (WPB*32*8)       // 4096
#define SM_VEXC_B (WPB*64*4)       // 4096
#define SM_INP_B  (WPB*64*4)       // 4096
#define SM_FIRE_B (WPB*2*4)        // 128
#define SM_CM_B   (CPB*4)          // 640
#define SM_ROW_B  32
#define SMEM_B (SM_EDGE_B+SM_ACT_B+SM_CNT_B+SM_PART_B+SM_VEXC_B+SM_INP_B+SM_FIRE_B+SM_CM_B+SM_ROW_B)

// ---------------- static device state ----------------
__device__ __align__(16) float    d_val[NSLOT*NCLS*BATCH];  // value ring [slot][cls][b]
__device__ __align__(16) uint32_t d_actb[NSLOT*ROWW];       // act bitmap ring (delivery rows)
__device__ __align__(16) float    d_inp[NHID*BATCH];
__device__ uint32_t d_hist[NN];
__device__ uint32_t d_off[NN+1];
__device__ uint32_t d_cursor[NN];
__device__ __align__(16) uint2    d_edge[NE];               // CSR by tgt: {cls | dm6<<21, w}
__device__ uint32_t d_flags[NBLK];

// ---------------- input GEMM ----------------
__global__ void gemm_kernel(const float* __restrict__ x, const float* __restrict__ W) {
    __shared__ float sx[8*NIN];
    int n  = blockIdx.x * 256 + threadIdx.x;
    int b0 = blockIdx.y * 8;
    for (int i = threadIdx.x; i < 8*NIN; i += 256) {
        int bb = i / NIN, kk = i - bb * NIN;
        sx[bb*NIN + kk] = x[(b0 + bb) * NIN + kk];
    }
    __syncthreads();
    float a[8];
#pragma unroll
    for (int bb = 0; bb < 8; bb++) a[bb] = 0.f;
#pragma unroll 4
    for (int k = 0; k < NIN; k++) {
        float w = W[k * NHID + n];
#pragma unroll
        for (int bb = 0; bb < 8; bb++) a[bb] += sx[bb*NIN + k] * w;
    }
#pragma unroll
    for (int bb = 0; bb < 8; bb++) d_inp[n*64 + b0 + bb] = a[bb];
}

// ---------------- distributed flag grid barrier ----------------
__device__ __forceinline__ void gridbar(uint32_t gen) {
    __syncthreads();
    if (threadIdx.x < 32) {
        __threadfence();
        if (threadIdx.x == 0) __stcg(&d_flags[blockIdx.x], gen);
        bool done = false;
        while (!done) {
            uint32_t mn = 0xFFFFFFFFu;
#pragma unroll
            for (int k = 0; k < 5; k++) {
                int i = threadIdx.x + k * 32;
                uint32_t v = (i < NBLK) ? __ldcg(&d_flags[i]) : 0xFFFFFFFFu;
                mn = min(mn, v);
            }
            done = __all_sync(0xffffffffu, mn >= gen);
            if (!done) __nanosleep(64);
        }
        __threadfence();
    }
    __syncthreads();
}

__device__ __forceinline__ uint32_t spread16(uint32_t x) {
    x &= 0xFFFFu;
    x = (x | (x << 8)) & 0x00FF00FFu;
    x = (x | (x << 4)) & 0x0F0F0F0Fu;
    x = (x | (x << 2)) & 0x33333333u;
    x = (x | (x << 1)) & 0x55555555u;
    return x;
}

// ---------------- launch phase (step u): block-local classes ----------------
__device__ __forceinline__ void launch_phase(int u, int bid,
        const uint32_t* __restrict__ s_cmeta, uint32_t* __restrict__ scnt,
        const uint32_t* __restrict__ s_fired, const float* __restrict__ s_vexc) {
    int wid = threadIdx.x >> 5, lane = threadIdx.x & 31;
    int sub = lane >> 4, q = lane & 15;
    int wslot = u & (NSLOT-1);
#pragma unroll
    for (int k = 0; k < 3; k++) {
        int cl = k * 64 + wid * 2 + sub;
        bool valid = (cl < CPB);
        int cli = valid ? cl : 0;
        uint32_t cm = s_cmeta[cli];
        uint32_t nl = cm & 0xFFFFu, d = cm >> 16;
        uint32_t lm = 0u;
        if (valid) {
            uint32_t fw = s_fired[nl*2 + (q >> 3)];
            uint32_t f4 = (fw >> ((q & 7) * 4)) & 15u;
            uint32_t c = scnt[cli*16 + q];
            uint32_t fm = ((f4 * 0x00204081u) & 0x01010101u) * 0xFFu;
            lm = __vcmpeq4(c, 0u) & fm;
            scnt[cli*16 + q] = __vsubus4(c, 0x01010101u) | (lm & (d * 0x01010101u));
        }
        uint32_t bal = __ballot_sync(0xffffffffu, lm != 0u);
        uint32_t halfact = (lane < 16) ? (bal & 0xFFFFu) : (bal >> 16);
        if (valid && halfact) {
            uint32_t cg = (uint32_t)bid * CPB + cl;
            if (q == 0) {
                int row = (u + (int)d) & (NSLOT-1);
                atomicOr(&d_actb[row*ROWW + (cg >> 5)], 1u << (cg & 31u));
            }
            const float4 ve = *(const float4*)&s_vexc[nl*64 + q*4];
            float4 o;
            o.x = (lm & 0x000000FFu) ? ve.x : 0.f;
            o.y = (lm & 0x0000FF00u) ? ve.y : 0.f;
            o.z = (lm & 0x00FF0000u) ? ve.z : 0.f;
            o.w = (lm & 0xFF000000u) ? ve.w : 0.f;
            *(float4*)&d_val[(unsigned)wslot * (NCLS*64) + cg*64 + q*4] = o;
        }
    }
}

// ---------------- consumer body (val via L1: safe, slots disjoint within region) ----------------
#define EDGE_BODY(ED)                                                            \
    {                                                                            \
        uint32_t cls = (ED).x & 0x7FFFu;                                         \
        if ((actrow[cls >> 5] >> (cls & 31u)) & 1u) {                            \
            uint32_t dm6 = (ED).x >> 21;                                         \
            uint32_t slot = (uu - dm6) & (NSLOT-1u);                             \
            float w = __uint_as_float((ED).y);                                   \
            float2 v = __ldg((const float2*)(valbase + slot*(NCLS*64) + cls*64)); \
            I0 += w * v.x;                                                       \
            I1 += w * v.y;                                                       \
        }                                                                        \
    }

__device__ __forceinline__ void consume_half(int u, int i0, int i1, int goff,
        bool fits, const uint2* __restrict__ s_edge, const uint32_t* __restrict__ actrow,
        float& I0, float& I1) {
    int lane = threadIdx.x & 31;
    const float* valbase = d_val + 2*lane;
    uint32_t uu = (uint32_t)(u - 6);
    if (fits) {
#pragma unroll 8
        for (int i = i0; i < i1; i++) { uint2 ed = s_edge[i]; EDGE_BODY(ed) }
    } else {
#pragma unroll 8
        for (int i = i0; i < i1; i++) { uint2 ed = __ldg(&d_edge[goff + i]); EDGE_BODY(ed) }
    }
}

// ---------------- persistent simulation kernel ----------------
__global__ void __launch_bounds__(NTHR, 1) sim_kernel(
        const float* __restrict__ We, const float* __restrict__ Le,
        const int* __restrict__ src, const int* __restrict__ tgt,
        float* __restrict__ out) {
    extern __shared__ uint8_t smem[];
    uint2*    s_edge  = (uint2*)smem;
    uint32_t* s_actw  = (uint32_t*)(smem + SM_EDGE_B);
    uint32_t* scnt    = (uint32_t*)(smem + SM_EDGE_B + SM_ACT_B);
    float2*   s_part  = (float2*)(smem + SM_EDGE_B + SM_ACT_B + SM_CNT_B);
    float*    s_vexc  = (float*)(smem + SM_EDGE_B + SM_ACT_B + SM_CNT_B + SM_PART_B);
    float*    s_inp   = (float*)(smem + SM_EDGE_B + SM_ACT_B + SM_CNT_B + SM_PART_B + SM_VEXC_B);
    uint32_t* s_fired = (uint32_t*)(smem + SM_EDGE_B + SM_ACT_B + SM_CNT_B + SM_PART_B + SM_VEXC_B + SM_INP_B);
    uint32_t* s_cmeta = (uint32_t*)(smem + SM_EDGE_B + SM_ACT_B + SM_CNT_B + SM_PART_B + SM_VEXC_B + SM_INP_B + SM_FIRE_B);
    uint32_t* s_rowany= (uint32_t*)(smem + SM_EDGE_B + SM_ACT_B + SM_CNT_B + SM_PART_B + SM_VEXC_B + SM_INP_B + SM_FIRE_B + SM_CM_B);

    int tid = threadIdx.x;
    int bid = blockIdx.x;
    int gtid = bid * NTHR + tid;
    uint32_t base = __ldcg(&d_flags[bid]);

    for (int i = tid; i < CPB*16; i += NTHR) scnt[i] = 0u;
    if (tid < CPB) s_cmeta[tid] = (uint32_t)(tid / 10) | (((uint32_t)(tid % 10) + 6u) << 16);

    // ---- 0. zero act ring + hist ----
    for (int i = gtid; i < NSLOT*ROWW; i += NBLK*NTHR) d_actb[i] = 0u;
    for (int i = gtid; i < NN; i += NBLK*NTHR) d_hist[i] = 0u;
    gridbar(base + 1);

    // ---- 1. histogram over targets ----
    for (int e = gtid; e < NE; e += NBLK*NTHR)
        atomicAdd(&d_hist[tgt[e]], 1u);
    gridbar(base + 2);

    // ---- 2. scan (block 0), scratch = s_edge ----
    if (bid == 0) {
        uint32_t* sa = (uint32_t*)s_edge;
        uint32_t* sb = sa + NN;
        for (int i = tid; i < NN; i += NTHR) sa[i] = d_hist[i];
        __syncthreads();
        uint32_t *pin = sa, *pout = sb;
        for (int off = 1; off < NN; off <<= 1) {
            for (int i = tid; i < NN; i += NTHR)
                pout[i] = pin[i] + (i >= off ? pin[i - off] : 0u);
            __syncthreads();
            uint32_t* t = pin; pin = pout; pout = t;
        }
        for (int i = tid; i < NN; i += NTHR) {
            d_off[i+1]  = pin[i];
            d_cursor[i] = (i > 0) ? pin[i-1] : 0u;
        }
        if (tid == 0) d_off[0] = 0u;
        __syncthreads();
    }
    gridbar(base + 3);

    // ---- 3. scatter into CSR ----
    for (int e = gtid; e < NE; e += NBLK*NTHR) {
        uint32_t dm6 = (uint32_t)(int)(Le[e] * 2.0f + 0.5f) - 6u;   // 0..9
        uint32_t s = (uint32_t)src[e];
        uint32_t pos = atomicAdd(&d_cursor[tgt[e]], 1u);
        d_edge[pos] = make_uint2((s*10u + dm6) | (dm6 << 21), __float_as_uint(We[e]));
    }
    gridbar(base + 4);

    // ---- 4. stage CSR segment + inp ----
    int n0 = bid * WPB;
    int blockBeg = 0; bool fits = false; int total = 0;
    {
        int nEnd = n0 + WPB; if (nEnd > NN) nEnd = NN;
        blockBeg = d_off[n0];
        total = d_off[nEnd] - blockBeg;
        fits = (total <= CAP);
        if (fits)
            for (int i = tid; i < total; i += NTHR)
                s_edge[i] = __ldg(&d_edge[blockBeg + i]);
    }
    if (bid < NBH) s_inp[tid] = d_inp[n0*64 + tid];
    __syncthreads();

    int wid = tid >> 5, lane = tid & 31;
    int pair = wid >> 1, half = wid & 1;
    int n = n0 + pair;
    bool nvalid = (n < NN);
    int cnt = 0, lbeg = 0, goff = 0;
    if (nvalid) {
        int beg = d_off[n], end = d_off[n+1];
        cnt = end - beg;
        lbeg = beg - blockBeg;
        goff = beg;
    }
    int h0 = cnt >> 1;
    int i0 = half ? h0 : 0;
    int i1 = half ? cnt : h0;

    float vm0 = 0.f, vm1 = 0.f, acc0 = 0.f, acc1 = 0.f;

    // ---- simulation: 5 regions x 6 steps, 1 gridbar per region ----
    for (int r = 0; r < 5; r++) {
        int u0 = r * 6;
        gridbar(base + 5 + r);
        if (tid < 6) s_rowany[tid] = 0u;
        __syncthreads();
        // stage act rows u0..u0+5 and compute per-row any-flags
        for (int i = tid; i < 6*ROWW; i += NTHR) {
            int j = i / ROWW, w = i - j*ROWW;
            uint32_t v = __ldcg(&d_actb[((u0 + j) & (NSLOT-1))*ROWW + w]);
            s_actw[i] = v;
            if (v) s_rowany[j] = 1u;          // benign race
        }
        // clear own words of rows consumed 2 regions ago
        if (bid < NBH && tid < 30) {
            int j = tid / 5, w = tid - (tid/5)*5;
            __stcg(&d_actb[((u0 - 12 + j + NSLOT) & (NSLOT-1))*ROWW + bid*5 + w], 0u);
        }
        __syncthreads();

        for (int j = 0; j < 6; j++) {
            int u = u0 + j;
            const uint32_t* actrow = s_actw + j*ROWW;
            bool rowact = s_rowany[j] != 0u;
            float I0 = 0.f, I1 = 0.f;
            if (rowact && nvalid && i1 > i0)
                consume_half(u, fits ? (lbeg + i0) : i0, fits ? (lbeg + i1) : i1,
                             goff, fits, s_edge, actrow, I0, I1);
            if (half == 1 && nvalid) s_part[pair*32 + lane] = make_float2(I0, I1);
            __syncthreads();
            if (nvalid && half == 0) {
                float2 p = s_part[pair*32 + lane];
                I0 += p.x; I1 += p.y;
                bool hid = n < NHID;
                if (hid && (u % 3) == 2) {
                    float2 ip = *(const float2*)&s_inp[pair*64 + 2*lane];
                    I0 += ip.x; I1 += ip.y;
                }
                vm0 += (I0 - vm0) * 0.1f;
                vm1 += (I1 - vm1) * 0.1f;
                if (!hid) { acc0 += vm0; acc1 += vm1; }
                else {
                    float ve0 = fmaxf(0.f, vm0 - 0.25f);
                    float ve1 = fmaxf(0.f, vm1 - 0.25f);
                    bool f0 = ve0 > 0.f, f1 = ve1 > 0.f;
                    if (f0) vm0 = -0.2f;
                    if (f1) vm1 = -0.2f;
                    *(float2*)&s_vexc[pair*64 + 2*lane] = make_float2(ve0, ve1);
                    uint32_t b0 = __ballot_sync(0xffffffffu, f0);
                    uint32_t b1 = __ballot_sync(0xffffffffu, f1);
                    uint32_t w0 = spread16(b0 & 0xFFFFu) | (spread16(b1 & 0xFFFFu) << 1);
                    uint32_t w1 = spread16(b0 >> 16)     | (spread16(b1 >> 16) << 1);
                    if (lane == 0) s_fired[pair*2]     = w0;
                    if (lane == 1) s_fired[pair*2 + 1] = w1;
                }
            } else if (half == 0) {
                __ballot_sync(0xffffffffu, false);
                __ballot_sync(0xffffffffu, false);
            }
            __syncthreads();
            if (bid < NBH) launch_phase(u, bid, s_cmeta, scnt, s_fired, s_vexc);
            __syncthreads();
        }
    }

    if (nvalid && half == 0 && n >= NHID) {
        int o = n - NHID;
        out[(2*lane)   * NOUT + o] = acc0 * (1.0f / (float)TSTEPS);
        out[(2*lane+1) * NOUT + o] = acc1 * (1.0f / (float)TSTEPS);
    }
}

extern "C" void kernel_launch(void* const* d_in, const int* in_sizes, int n_in,
                              void* d_out, int out_size) {
    const float* x   = (const float*)d_in[0];
    const float* W   = (const float*)d_in[1];
    const float* We  = (const float*)d_in[2];
    const float* Le  = (const float*)d_in[3];
    const int*   src = (const int*)d_in[4];
    const int*   tgt = (const int*)d_in[5];
    float* out = (float*)d_out;
    (void)in_sizes; (void)n_in; (void)out_size;

    cudaFuncSetAttribute(sim_kernel, cudaFuncAttributeMaxDynamicSharedMemorySize, SMEM_B);
    dim3 gg(8, 8);
    gemm_kernel<<<gg, 256>>>(x, W);
    sim_kernel<<<NBLK, NTHR, SMEM_B>>>(We, Le, src, tgt, out);
}

// round 13
// speedup vs baseline: 8.6454x; 1.3155x over previous
#include <cuda_runtime.h>
#include <stdint.h>

#define BATCH  64
#define NIN    784
#define NHID   2048
#define NOUT   10
#define NN     2058
#define NE     262144
#define TSTEPS 30
#define NBH    128                 // blocks owning hidden neurons+classes
#define NBLK   129                 // + 1 output block
#define NTHR   1024
#define WPB    16                  // neurons per block
#define NCLS   (NHID*10)           // 20480 classes (src, delay)
#define CPB    160                 // classes per hidden block
#define ROWW   (NCLS/32)           // 640 words per act row
#define NSLOT  32                  // ring depth
#define CAP    2560
#define BCAP   112                 // bucket entries per warp

// dynamic smem layout (bytes)
#define SM_EDGE_B (CAP*8)          // 20480
#define SM_ACT_B  (6*ROWW*4)       // 15360
#define SM_CNT_B  (CPB*16*4)       // 10240
#define SM_PART_B (WPB*32*8)       // 4096
#define SM_VEXC_B (WPB*64*4)       // 4096
#define SM_INP_B  (WPB*64*4)       // 4096
#define SM_FIRE_B (WPB*2*4)        // 128
#define SM_CM_B   (CPB*4)          // 640
#define SM_ROW_B  32
#define SM_BUCK_B (32*BCAP*8)      // 28672
#define SMEM_B (SM_EDGE_B+SM_ACT_B+SM_CNT_B+SM_PART_B+SM_VEXC_B+SM_INP_B+SM_FIRE_B+SM_CM_B+SM_ROW_B+SM_BUCK_B)

// ---------------- static device state ----------------
__device__ __align__(16) float    d_val[NSLOT*NCLS*BATCH];  // value ring [slot][cls][b]
__device__ __align__(16) uint32_t d_actb[NSLOT*ROWW];       // act bitmap ring (delivery rows)
__device__ __align__(16) float    d_inp[NHID*BATCH];
__device__ uint32_t d_hist[NN];
__device__ uint32_t d_off[NN+1];
__device__ uint32_t d_cursor[NN];
__device__ __align__(16) uint2    d_edge[NE];               // CSR by tgt: {cls | dm6<<21, w}
__device__ uint32_t d_flags[NBLK];

// ---------------- input GEMM ----------------
__global__ void gemm_kernel(const float* __restrict__ x, const float* __restrict__ W) {
    __shared__ float sx[8*NIN];
    int n  = blockIdx.x * 256 + threadIdx.x;
    int b0 = blockIdx.y * 8;
    for (int i = threadIdx.x; i < 8*NIN; i += 256) {
        int bb = i / NIN, kk = i - bb * NIN;
        sx[bb*NIN + kk] = x[(b0 + bb) * NIN + kk];
    }
    __syncthreads();
    float a[8];
#pragma unroll
    for (int bb = 0; bb < 8; bb++) a[bb] = 0.f;
#pragma unroll 4
    for (int k = 0; k < NIN; k++) {
        float w = W[k * NHID + n];
#pragma unroll
        for (int bb = 0; bb < 8; bb++) a[bb] += sx[bb*NIN + k] * w;
    }
#pragma unroll
    for (int bb = 0; bb < 8; bb++) d_inp[n*64 + b0 + bb] = a[bb];
}

// ---------------- distributed flag grid barrier ----------------
__device__ __forceinline__ void gridbar(uint32_t gen) {
    __syncthreads();
    if (threadIdx.x < 32) {
        __threadfence();
        if (threadIdx.x == 0) __stcg(&d_flags[blockIdx.x], gen);
        bool done = false;
        while (!done) {
            uint32_t mn = 0xFFFFFFFFu;
#pragma unroll
            for (int k = 0; k < 5; k++) {
                int i = threadIdx.x + k * 32;
                uint32_t v = (i < NBLK) ? __ldcg(&d_flags[i]) : 0xFFFFFFFFu;
                mn = min(mn, v);
            }
            done = __all_sync(0xffffffffu, mn >= gen);
            if (!done) __nanosleep(64);
        }
        __threadfence();
    }
    __syncthreads();
}

__device__ __forceinline__ uint32_t spread16(uint32_t x) {
    x &= 0xFFFFu;
    x = (x | (x << 8)) & 0x00FF00FFu;
    x = (x | (x << 4)) & 0x0F0F0F0Fu;
    x = (x | (x << 2)) & 0x33333333u;
    x = (x | (x << 1)) & 0x55555555u;
    return x;
}

// ---------------- launch phase (step u): block-local classes ----------------
__device__ __forceinline__ void launch_phase(int u, int bid,
        const uint32_t* __restrict__ s_cmeta, uint32_t* __restrict__ scnt,
        const uint32_t* __restrict__ s_fired, const float* __restrict__ s_vexc) {
    int wid = threadIdx.x >> 5, lane = threadIdx.x & 31;
    int sub = lane >> 4, q = lane & 15;
    int wslot = u & (NSLOT-1);
#pragma unroll
    for (int k = 0; k < 3; k++) {
        int cl = k * 64 + wid * 2 + sub;
        bool valid = (cl < CPB);
        int cli = valid ? cl : 0;
        uint32_t cm = s_cmeta[cli];
        uint32_t nl = cm & 0xFFFFu, d = cm >> 16;
        uint32_t lm = 0u;
        if (valid) {
            uint32_t fw = s_fired[nl*2 + (q >> 3)];
            uint32_t f4 = (fw >> ((q & 7) * 4)) & 15u;
            uint32_t c = scnt[cli*16 + q];
            uint32_t fm = ((f4 * 0x00204081u) & 0x01010101u) * 0xFFu;
            lm = __vcmpeq4(c, 0u) & fm;
            scnt[cli*16 + q] = __vsubus4(c, 0x01010101u) | (lm & (d * 0x01010101u));
        }
        uint32_t bal = __ballot_sync(0xffffffffu, lm != 0u);
        uint32_t halfact = (lane < 16) ? (bal & 0xFFFFu) : (bal >> 16);
        if (valid && halfact) {
            uint32_t cg = (uint32_t)bid * CPB + cl;
            if (q == 0) {
                int row = (u + (int)d) & (NSLOT-1);
                atomicOr(&d_actb[row*ROWW + (cg >> 5)], 1u << (cg & 31u));
            }
            const float4 ve = *(const float4*)&s_vexc[nl*64 + q*4];
            float4 o;
            o.x = (lm & 0x000000FFu) ? ve.x : 0.f;
            o.y = (lm & 0x0000FF00u) ? ve.y : 0.f;
            o.z = (lm & 0x00FF0000u) ? ve.z : 0.f;
            o.w = (lm & 0xFF000000u) ? ve.w : 0.f;
            *(float4*)&d_val[(unsigned)wslot * (NCLS*64) + cg*64 + q*4] = o;
        }
    }
}

// ---------------- fallback consumer body (unfiltered scan) ----------------
#define EDGE_BODY(ED)                                                            \
    {                                                                            \
        uint32_t cls = (ED).x & 0x7FFFu;                                         \
        if ((actrow[cls >> 5] >> (cls & 31u)) & 1u) {                            \
            uint32_t dm6 = (ED).x >> 21;                                         \
            uint32_t slot = (uu - dm6) & (NSLOT-1u);                             \
            float w = __uint_as_float((ED).y);                                   \
            float2 v = __ldg((const float2*)(valbase + slot*(NCLS*64) + cls*64)); \
            I0 += w * v.x;                                                       \
            I1 += w * v.y;                                                       \
        }                                                                        \
    }

// ---------------- warp-parallel filter + compact consume ----------------
__device__ __forceinline__ void filter_consume(int u, int i0, int i1, int goff, bool fits,
        const uint2* __restrict__ s_edge, const uint32_t* __restrict__ actrow,
        uint2* __restrict__ buck, float& I0, float& I1) {
    int lane = threadIdx.x & 31;
    const float* valbase = d_val + 2*lane;
    uint32_t uu = (uint32_t)(u - 6);
    int cnt = i1 - i0;
    if (cnt <= 0) return;
    if (cnt <= BCAP) {
        // filter: one lane per edge, compact in order
        int m = 0;
        for (int i = i0; i < i1; i += 32) {
            int e = i + lane;
            bool pass = false;
            uint2 ed = make_uint2(0u, 0u);
            if (e < i1) {
                ed = fits ? s_edge[e] : __ldg(&d_edge[goff + e]);
                uint32_t cls = ed.x & 0x7FFFu;
                pass = (actrow[cls >> 5] >> (cls & 31u)) & 1u;
            }
            uint32_t bal = __ballot_sync(0xffffffffu, pass);
            if (pass) {
                uint32_t cls = ed.x & 0x7FFFu;
                uint32_t dm6 = ed.x >> 21;
                uint32_t slot = (uu - dm6) & (NSLOT-1u);
                int pos = m + __popc(bal & ((1u << lane) - 1u));
                buck[pos] = make_uint2(slot*(NCLS*64u) + cls*64u, ed.y);
            }
            m += __popc(bal);
        }
        // consume compact list (broadcast LDS + LDG + FMA)
#pragma unroll 4
        for (int t = 0; t < m; t++) {
            uint2 en = buck[t];
            float w = __uint_as_float(en.y);
            float2 v = __ldg((const float2*)(valbase + en.x));
            I0 += w * v.x;
            I1 += w * v.y;
        }
    } else {
        // fallback: uniform scan
        if (fits) {
#pragma unroll 8
            for (int i = i0; i < i1; i++) { uint2 ed = s_edge[i]; EDGE_BODY(ed) }
        } else {
#pragma unroll 8
            for (int i = i0; i < i1; i++) { uint2 ed = __ldg(&d_edge[goff + i]); EDGE_BODY(ed) }
        }
    }
}

// ---------------- persistent simulation kernel ----------------
__global__ void __launch_bounds__(NTHR, 1) sim_kernel(
        const float* __restrict__ We, const float* __restrict__ Le,
        const int* __restrict__ src, const int* __restrict__ tgt,
        float* __restrict__ out) {
    extern __shared__ uint8_t smem[];
    uint2*    s_edge  = (uint2*)smem;
    uint32_t* s_actw  = (uint32_t*)(smem + SM_EDGE_B);
    uint32_t* scnt    = (uint32_t*)(smem + SM_EDGE_B + SM_ACT_B);
    float2*   s_part  = (float2*)(smem + SM_EDGE_B + SM_ACT_B + SM_CNT_B);
    float*    s_vexc  = (float*)(smem + SM_EDGE_B + SM_ACT_B + SM_CNT_B + SM_PART_B);
    float*    s_inp   = (float*)(smem + SM_EDGE_B + SM_ACT_B + SM_CNT_B + SM_PART_B + SM_VEXC_B);
    uint32_t* s_fired = (uint32_t*)(smem + SM_EDGE_B + SM_ACT_B + SM_CNT_B + SM_PART_B + SM_VEXC_B + SM_INP_B);
    uint32_t* s_cmeta = (uint32_t*)(smem + SM_EDGE_B + SM_ACT_B + SM_CNT_B + SM_PART_B + SM_VEXC_B + SM_INP_B + SM_FIRE_B);
    uint32_t* s_rowany= (uint32_t*)(smem + SM_EDGE_B + SM_ACT_B + SM_CNT_B + SM_PART_B + SM_VEXC_B + SM_INP_B + SM_FIRE_B + SM_CM_B);
    uint2*    s_buck  = (uint2*)(smem + SM_EDGE_B + SM_ACT_B + SM_CNT_B + SM_PART_B + SM_VEXC_B + SM_INP_B + SM_FIRE_B + SM_CM_B + SM_ROW_B);

    int tid = threadIdx.x;
    int bid = blockIdx.x;
    int gtid = bid * NTHR + tid;
    uint32_t base = __ldcg(&d_flags[bid]);

    for (int i = tid; i < CPB*16; i += NTHR) scnt[i] = 0u;
    if (tid < CPB) s_cmeta[tid] = (uint32_t)(tid / 10) | (((uint32_t)(tid % 10) + 6u) << 16);

    // ---- 0. zero act ring + hist ----
    for (int i = gtid; i < NSLOT*ROWW; i += NBLK*NTHR) d_actb[i] = 0u;
    for (int i = gtid; i < NN; i += NBLK*NTHR) d_hist[i] = 0u;
    gridbar(base + 1);

    // ---- 1. histogram over targets ----
    for (int e = gtid; e < NE; e += NBLK*NTHR)
        atomicAdd(&d_hist[tgt[e]], 1u);
    gridbar(base + 2);

    // ---- 2. scan (block 0), scratch = s_edge ----
    if (bid == 0) {
        uint32_t* sa = (uint32_t*)s_edge;
        uint32_t* sb = sa + NN;
        for (int i = tid; i < NN; i += NTHR) sa[i] = d_hist[i];
        __syncthreads();
        uint32_t *pin = sa, *pout = sb;
        for (int off = 1; off < NN; off <<= 1) {
            for (int i = tid; i < NN; i += NTHR)
                pout[i] = pin[i] + (i >= off ? pin[i - off] : 0u);
            __syncthreads();
            uint32_t* t = pin; pin = pout; pout = t;
        }
        for (int i = tid; i < NN; i += NTHR) {
            d_off[i+1]  = pin[i];
            d_cursor[i] = (i > 0) ? pin[i-1] : 0u;
        }
        if (tid == 0) d_off[0] = 0u;
        __syncthreads();
    }
    gridbar(base + 3);

    // ---- 3. scatter into CSR ----
    for (int e = gtid; e < NE; e += NBLK*NTHR) {
        uint32_t dm6 = (uint32_t)(int)(Le[e] * 2.0f + 0.5f) - 6u;   // 0..9
        uint32_t s = (uint32_t)src[e];
        uint32_t pos = atomicAdd(&d_cursor[tgt[e]], 1u);
        d_edge[pos] = make_uint2((s*10u + dm6) | (dm6 << 21), __float_as_uint(We[e]));
    }
    gridbar(base + 4);

    // ---- 4. stage CSR segment + inp ----
    int n0 = bid * WPB;
    int blockBeg = 0; bool fits = false; int total = 0;
    {
        int nEnd = n0 + WPB; if (nEnd > NN) nEnd = NN;
        blockBeg = d_off[n0];
        total = d_off[nEnd] - blockBeg;
        fits = (total <= CAP);
        if (fits)
            for (int i = tid; i < total; i += NTHR)
                s_edge[i] = __ldg(&d_edge[blockBeg + i]);
    }
    if (bid < NBH) s_inp[tid] = d_inp[n0*64 + tid];
    __syncthreads();

    int wid = tid >> 5, lane = tid & 31;
    int pair = wid >> 1, half = wid & 1;
    int n = n0 + pair;
    bool nvalid = (n < NN);
    int cnt = 0, lbeg = 0, goff = 0;
    if (nvalid) {
        int beg = d_off[n], end = d_off[n+1];
        cnt = end - beg;
        lbeg = beg - blockBeg;
        goff = beg;
    }
    int h0 = cnt >> 1;
    int i0 = half ? h0 : 0;
    int i1 = half ? cnt : h0;
    uint2* mybuck = s_buck + wid * BCAP;

    float vm0 = 0.f, vm1 = 0.f, acc0 = 0.f, acc1 = 0.f;

    // ---- simulation: 5 regions x 6 steps, 1 gridbar per region ----
    for (int r = 0; r < 5; r++) {
        int u0 = r * 6;
        gridbar(base + 5 + r);
        if (tid < 6) s_rowany[tid] = 0u;
        __syncthreads();
        // stage act rows u0..u0+5 and compute per-row any-flags
        for (int i = tid; i < 6*ROWW; i += NTHR) {
            int j = i / ROWW, w = i - j*ROWW;
            uint32_t v = __ldcg(&d_actb[((u0 + j) & (NSLOT-1))*ROWW + w]);
            s_actw[i] = v;
            if (v) s_rowany[j] = 1u;          // benign race
        }
        // clear own words of rows consumed 2 regions ago
        if (bid < NBH && tid < 30) {
            int j = tid / 5, w = tid - (tid/5)*5;
            __stcg(&d_actb[((u0 - 12 + j + NSLOT) & (NSLOT-1))*ROWW + bid*5 + w], 0u);
        }
        __syncthreads();

        for (int j = 0; j < 6; j++) {
            int u = u0 + j;
            const uint32_t* actrow = s_actw + j*ROWW;
            bool rowact = s_rowany[j] != 0u;
            float I0 = 0.f, I1 = 0.f;
            if (rowact && nvalid)
                filter_consume(u, fits ? (lbeg + i0) : i0, fits ? (lbeg + i1) : i1,
                               goff - (fits ? lbeg : 0), fits, s_edge, actrow,
                               mybuck, I0, I1);
            if (half == 1 && nvalid) s_part[pair*32 + lane] = make_float2(I0, I1);
            __syncthreads();
            if (nvalid && half == 0) {
                float2 p = s_part[pair*32 + lane];
                I0 += p.x; I1 += p.y;
                bool hid = n < NHID;
                if (hid && (u % 3) == 2) {
                    float2 ip = *(const float2*)&s_inp[pair*64 + 2*lane];
                    I0 += ip.x; I1 += ip.y;
                }
                vm0 += (I0 - vm0) * 0.1f;
                vm1 += (I1 - vm1) * 0.1f;
                if (!hid) { acc0 += vm0; acc1 += vm1; }
                else {
                    float ve0 = fmaxf(0.f, vm0 - 0.25f);
                    float ve1 = fmaxf(0.f, vm1 - 0.25f);
                    bool f0 = ve0 > 0.f, f1 = ve1 > 0.f;
                    if (f0) vm0 = -0.2f;
                    if (f1) vm1 = -0.2f;
                    *(float2*)&s_vexc[pair*64 + 2*lane] = make_float2(ve0, ve1);
                    uint32_t b0 = __ballot_sync(0xffffffffu, f0);
                    uint32_t b1 = __ballot_sync(0xffffffffu, f1);
                    uint32_t w0 = spread16(b0 & 0xFFFFu) | (spread16(b1 & 0xFFFFu) << 1);
                    uint32_t w1 = spread16(b0 >> 16)     | (spread16(b1 >> 16) << 1);
                    if (lane == 0) s_fired[pair*2]     = w0;
                    if (lane == 1) s_fired[pair*2 + 1] = w1;
                }
            } else if (half == 0) {
                __ballot_sync(0xffffffffu, false);
                __ballot_sync(0xffffffffu, false);
            }
            __syncthreads();
            if (bid < NBH) launch_phase(u, bid, s_cmeta, scnt, s_fired, s_vexc);
            __syncthreads();
        }
    }

    if (nvalid && half == 0 && n >= NHID) {
        int o = n - NHID;
        out[(2*lane)   * NOUT + o] = acc0 * (1.0f / (float)TSTEPS);
        out[(2*lane+1) * NOUT + o] = acc1 * (1.0f / (float)TSTEPS);
    }
}

extern "C" void kernel_launch(void* const* d_in, const int* in_sizes, int n_in,
                              void* d_out, int out_size) {
    const float* x   = (const float*)d_in[0];
    const float* W   = (const float*)d_in[1];
    const float* We  = (const float*)d_in[2];
    const float* Le  = (const float*)d_in[3];
    const int*   src = (const int*)d_in[4];
    const int*   tgt = (const int*)d_in[5];
    float* out = (float*)d_out;
    (void)in_sizes; (void)n_in; (void)out_size;

    cudaFuncSetAttribute(sim_kernel, cudaFuncAttributeMaxDynamicSharedMemorySize, SMEM_B);
    dim3 gg(8, 8);
    gemm_kernel<<<gg, 256>>>(x, W);
    sim_kernel<<<NBLK, NTHR, SMEM_B>>>(We, Le, src, tgt, out);
}

// round 14
// speedup vs baseline: 8.8488x; 1.0235x over previous
#include <cuda_runtime.h>
#include <stdint.h>

#define BATCH  64
#define NIN    784
#define NHID   2048
#define NOUT   10
#define NN     2058
#define NE     262144
#define TSTEPS 30
#define NBLK   148
#define NBACT  147                 // blocks 0..146 own neurons (147*14 = 2058)
#define NTHR   1024
#define WPB    14                  // neurons per block
#define NCLS   (NHID*10)           // 20480 classes (src, delay)
#define CPB    (WPB*10)            // 140 class slots per block
#define ROWW   (NCLS/32)           // 640 words per act row
#define NSLOT  32                  // ring depth
#define CAP    2560
#define BCAP   112                 // bucket entries per warp

// dynamic smem layout (bytes)
#define SM_EDGE_B (CAP*8)          // 20480
#define SM_ACT_B  (6*ROWW*4)       // 15360
#define SM_DL_B   (CPB*16*4)       // 8960
#define SM_PART_B (16*32*8)        // 4096
#define SM_VEXC_B (2*WPB*64*4)     // 7168
#define SM_INP_B  (WPB*64*4)       // 3584
#define SM_FIRE_B (2*WPB*2*4)      // 224 -> 256
#define SM_CM_B   576
#define SM_ROW_B  32
#define SM_BUCK_B (32*BCAP*8)      // 28672
#define SMEM_B (SM_EDGE_B+SM_ACT_B+SM_DL_B+SM_PART_B+SM_VEXC_B+SM_INP_B+256+SM_CM_B+SM_ROW_B+SM_BUCK_B)

// ---------------- static device state ----------------
__device__ __align__(16) float    d_val[NSLOT*NCLS*BATCH];  // value ring [slot][cls][b]
__device__ __align__(16) uint32_t d_actb[NSLOT*ROWW];       // act bitmap ring (delivery rows)
__device__ __align__(16) float    d_inp[NHID*BATCH];
__device__ uint32_t d_hist[NN];
__device__ uint32_t d_off[NN+1];
__device__ uint32_t d_cursor[NN];
__device__ __align__(16) uint2    d_edge[NE];               // CSR by tgt: {cls | dm6<<21, w}
__device__ uint32_t d_flags[NBLK];

// ---------------- input GEMM ----------------
__global__ void gemm_kernel(const float* __restrict__ x, const float* __restrict__ W) {
    __shared__ float sx[8*NIN];
    int n  = blockIdx.x * 256 + threadIdx.x;
    int b0 = blockIdx.y * 8;
    for (int i = threadIdx.x; i < 8*NIN; i += 256) {
        int bb = i / NIN, kk = i - bb * NIN;
        sx[bb*NIN + kk] = x[(b0 + bb) * NIN + kk];
    }
    __syncthreads();
    float a[8];
#pragma unroll
    for (int bb = 0; bb < 8; bb++) a[bb] = 0.f;
#pragma unroll 4
    for (int k = 0; k < NIN; k++) {
        float w = W[k * NHID + n];
#pragma unroll
        for (int bb = 0; bb < 8; bb++) a[bb] += sx[bb*NIN + k] * w;
    }
#pragma unroll
    for (int bb = 0; bb < 8; bb++) d_inp[n*64 + b0 + bb] = a[bb];
}

// ---------------- distributed flag grid barrier ----------------
__device__ __forceinline__ void gridbar(uint32_t gen) {
    __syncthreads();
    if (threadIdx.x < 32) {
        __threadfence();
        if (threadIdx.x == 0) __stcg(&d_flags[blockIdx.x], gen);
        bool done = false;
        while (!done) {
            uint32_t mn = 0xFFFFFFFFu;
#pragma unroll
            for (int k = 0; k < 5; k++) {
                int i = threadIdx.x + k * 32;
                uint32_t v = (i < NBLK) ? __ldcg(&d_flags[i]) : 0xFFFFFFFFu;
                mn = min(mn, v);
            }
            done = __all_sync(0xffffffffu, mn >= gen);
            if (!done) __nanosleep(64);
        }
        __threadfence();
    }
    __syncthreads();
}

__device__ __forceinline__ uint32_t spread16(uint32_t x) {
    x &= 0xFFFFu;
    x = (x | (x << 8)) & 0x00FF00FFu;
    x = (x | (x << 4)) & 0x0F0F0F0Fu;
    x = (x | (x << 2)) & 0x33333333u;
    x = (x | (x << 1)) & 0x55555555u;
    return x;
}

// ---------------- launch phase (step u): deadline-based, fired-gated ----------------
__device__ __forceinline__ void launch_phase(int u, int bid,
        const uint32_t* __restrict__ s_cmeta, uint32_t* __restrict__ s_dl,
        const uint32_t* __restrict__ s_fired, const float* __restrict__ s_vexc) {
    int wid = threadIdx.x >> 5, lane = threadIdx.x & 31;
    int sub = lane >> 4, q = lane & 15;
    int wslot = u & (NSLOT-1);
    uint32_t ub = (uint32_t)u * 0x01010101u;
#pragma unroll
    for (int k = 0; k < 3; k++) {
        int cl = k * 64 + wid * 2 + sub;
        bool valid = (cl < CPB);
        int cli = valid ? cl : 0;
        uint32_t cm = s_cmeta[cli];
        valid = valid && (cm != 0xFFFFFFFFu);
        uint32_t nl = cm & 0xFFFFu, d = cm >> 16;
        uint32_t lm = 0u;
        if (valid) {
            uint32_t fw = s_fired[nl*2 + (q >> 3)];
            uint32_t f4 = (fw >> ((q & 7) * 4)) & 15u;
            if (f4) {
                uint32_t fm = ((f4 * 0x00204081u) & 0x01010101u) * 0xFFu;
                uint32_t dl = s_dl[cli*16 + q];
                lm = fm & __vcmpgeu4(ub, dl);
                if (lm)
                    s_dl[cli*16 + q] = (~lm & dl) | (lm & (((uint32_t)u + d + 1u) * 0x01010101u));
            }
        }
        uint32_t bal = __ballot_sync(0xffffffffu, lm != 0u);
        uint32_t halfact = (lane < 16) ? (bal & 0xFFFFu) : (bal >> 16);
        if (valid && halfact) {
            uint32_t cg = (uint32_t)bid * CPB + cl;
            if (q == 0) {
                int row = (u + (int)d) & (NSLOT-1);
                atomicOr(&d_actb[row*ROWW + (cg >> 5)], 1u << (cg & 31u));
            }
            const float4 ve = *(const float4*)&s_vexc[nl*64 + q*4];
            float4 o;
            o.x = (lm & 0x000000FFu) ? ve.x : 0.f;
            o.y = (lm & 0x0000FF00u) ? ve.y : 0.f;
            o.z = (lm & 0x00FF0000u) ? ve.z : 0.f;
            o.w = (lm & 0xFF000000u) ? ve.w : 0.f;
            *(float4*)&d_val[(unsigned)wslot * (NCLS*64) + cg*64 + q*4] = o;
        }
    }
}

// ---------------- fallback consumer body ----------------
#define EDGE_BODY(ED)                                                            \
    {                                                                            \
        uint32_t cls = (ED).x & 0x7FFFu;                                         \
        if ((actrow[cls >> 5] >> (cls & 31u)) & 1u) {                            \
            uint32_t dm6 = (ED).x >> 21;                                         \
            uint32_t slot = (uu - dm6) & (NSLOT-1u);                             \
            float w = __uint_as_float((ED).y);                                   \
            float2 v = __ldg((const float2*)(valbase + slot*(NCLS*64) + cls*64)); \
            I0 += w * v.x;                                                       \
            I1 += w * v.y;                                                       \
        }                                                                        \
    }

// ---------------- warp-parallel filter + compact consume ----------------
__device__ __forceinline__ void filter_consume(int u, int i0, int i1, int goff, bool fits,
        const uint2* __restrict__ s_edge, const uint32_t* __restrict__ actrow,
        uint2* __restrict__ buck, float& I0, float& I1) {
    int lane = threadIdx.x & 31;
    const float* valbase = d_val + 2*lane;
    uint32_t uu = (uint32_t)(u - 6);
    int cnt = i1 - i0;
    if (cnt <= 0) return;
    if (cnt <= BCAP) {
        int m = 0;
        for (int i = i0; i < i1; i += 32) {
            int e = i + lane;
            bool pass = false;
            uint2 ed = make_uint2(0u, 0u);
            if (e < i1) {
                ed = fits ? s_edge[e] : __ldg(&d_edge[goff + e]);
                uint32_t cls = ed.x & 0x7FFFu;
                pass = (actrow[cls >> 5] >> (cls & 31u)) & 1u;
            }
            uint32_t bal = __ballot_sync(0xffffffffu, pass);
            if (pass) {
                uint32_t cls = ed.x & 0x7FFFu;
                uint32_t dm6 = ed.x >> 21;
                uint32_t slot = (uu - dm6) & (NSLOT-1u);
                int pos = m + __popc(bal & ((1u << lane) - 1u));
                buck[pos] = make_uint2(slot*(NCLS*64u) + cls*64u, ed.y);
            }
            m += __popc(bal);
        }
#pragma unroll 4
        for (int t = 0; t < m; t++) {
            uint2 en = buck[t];
            float w = __uint_as_float(en.y);
            float2 v = __ldg((const float2*)(valbase + en.x));
            I0 += w * v.x;
            I1 += w * v.y;
        }
    } else {
        if (fits) {
#pragma unroll 8
            for (int i = i0; i < i1; i++) { uint2 ed = s_edge[i]; EDGE_BODY(ed) }
        } else {
#pragma unroll 8
            for (int i = i0; i < i1; i++) { uint2 ed = __ldg(&d_edge[goff + i]); EDGE_BODY(ed) }
        }
    }
}

// ---------------- persistent simulation kernel ----------------
__global__ void __launch_bounds__(NTHR, 1) sim_kernel(
        const float* __restrict__ We, const float* __restrict__ Le,
        const int* __restrict__ src, const int* __restrict__ tgt,
        float* __restrict__ out) {
    extern __shared__ uint8_t smem[];
    uint2*    s_edge  = (uint2*)smem;
    uint32_t* s_actw  = (uint32_t*)(smem + SM_EDGE_B);
    uint32_t* s_dl    = (uint32_t*)(smem + SM_EDGE_B + SM_ACT_B);
    float2*   s_part  = (float2*)(smem + SM_EDGE_B + SM_ACT_B + SM_DL_B);
    float*    s_vexc  = (float*)(smem + SM_EDGE_B + SM_ACT_B + SM_DL_B + SM_PART_B);
    float*    s_inp   = (float*)(smem + SM_EDGE_B + SM_ACT_B + SM_DL_B + SM_PART_B + SM_VEXC_B);
    uint32_t* s_fired = (uint32_t*)(smem + SM_EDGE_B + SM_ACT_B + SM_DL_B + SM_PART_B + SM_VEXC_B + SM_INP_B);
    uint32_t* s_cmeta = (uint32_t*)(smem + SM_EDGE_B + SM_ACT_B + SM_DL_B + SM_PART_B + SM_VEXC_B + SM_INP_B + 256);
    uint32_t* s_rowany= (uint32_t*)(smem + SM_EDGE_B + SM_ACT_B + SM_DL_B + SM_PART_B + SM_VEXC_B + SM_INP_B + 256 + SM_CM_B);
    uint2*    s_buck  = (uint2*)(smem + SM_EDGE_B + SM_ACT_B + SM_DL_B + SM_PART_B + SM_VEXC_B + SM_INP_B + 256 + SM_CM_B + SM_ROW_B);

    int tid = threadIdx.x;
    int bid = blockIdx.x;
    int gtid = bid * NTHR + tid;
    int n0 = bid * WPB;
    uint32_t base = __ldcg(&d_flags[bid]);

    for (int i = tid; i < CPB*16; i += NTHR) s_dl[i] = 0u;   // deadline 0 -> eligible
    if (tid < CPB) {
        int nl = tid / 10, d = tid % 10 + 6;
        bool v = (bid < NBACT) && (n0 + nl < NHID);
        s_cmeta[tid] = v ? ((uint32_t)nl | ((uint32_t)d << 16)) : 0xFFFFFFFFu;
    }

    // ---- 0. zero act ring + hist ----
    for (int i = gtid; i < NSLOT*ROWW; i += NBLK*NTHR) d_actb[i] = 0u;
    for (int i = gtid; i < NN; i += NBLK*NTHR) d_hist[i] = 0u;
    gridbar(base + 1);

    // ---- 1. histogram over targets ----
    for (int e = gtid; e < NE; e += NBLK*NTHR)
        atomicAdd(&d_hist[tgt[e]], 1u);
    gridbar(base + 2);

    // ---- 2. scan (block 0), scratch = s_edge ----
    if (bid == 0) {
        uint32_t* sa = (uint32_t*)s_edge;
        uint32_t* sb = sa + NN;
        for (int i = tid; i < NN; i += NTHR) sa[i] = d_hist[i];
        __syncthreads();
        uint32_t *pin = sa, *pout = sb;
        for (int off = 1; off < NN; off <<= 1) {
            for (int i = tid; i < NN; i += NTHR)
                pout[i] = pin[i] + (i >= off ? pin[i - off] : 0u);
            __syncthreads();
            uint32_t* t = pin; pin = pout; pout = t;
        }
        for (int i = tid; i < NN; i += NTHR) {
            d_off[i+1]  = pin[i];
            d_cursor[i] = (i > 0) ? pin[i-1] : 0u;
        }
        if (tid == 0) d_off[0] = 0u;
        __syncthreads();
    }
    gridbar(base + 3);

    // ---- 3. scatter into CSR ----
    for (int e = gtid; e < NE; e += NBLK*NTHR) {
        uint32_t dm6 = (uint32_t)(int)(Le[e] * 2.0f + 0.5f) - 6u;   // 0..9
        uint32_t s = (uint32_t)src[e];
        uint32_t pos = atomicAdd(&d_cursor[tgt[e]], 1u);
        d_edge[pos] = make_uint2((s*10u + dm6) | (dm6 << 21), __float_as_uint(We[e]));
    }
    gridbar(base + 4);

    // ---- 4. stage CSR segment + inp ----
    int blockBeg = 0; bool fits = false; int total = 0;
    int hidcnt = 0;
    if (bid < NBACT) {
        hidcnt = (n0 < NHID) ? min(WPB, NHID - n0) : 0;
        int nEnd = n0 + WPB; if (nEnd > NN) nEnd = NN;
        blockBeg = d_off[n0];
        total = d_off[nEnd] - blockBeg;
        fits = (total <= CAP);
        if (fits)
            for (int i = tid; i < total; i += NTHR)
                s_edge[i] = __ldg(&d_edge[blockBeg + i]);
        if (tid < hidcnt*64) s_inp[tid] = d_inp[n0*64 + tid];
    }
    __syncthreads();

    int wid = tid >> 5, lane = tid & 31;
    int pair = wid >> 1, half = wid & 1;
    int n = n0 + pair;
    bool nvalid = (bid < NBACT) && (pair < WPB) && (n < NN);
    int cnt = 0, lbeg = 0, goff = 0;
    if (nvalid) {
        int beg = d_off[n], end = d_off[n+1];
        cnt = end - beg;
        lbeg = beg - blockBeg;
        goff = beg;
    }
    int h0 = cnt >> 1;
    int i0 = half ? h0 : 0;
    int i1 = half ? cnt : h0;
    uint2* mybuck = s_buck + wid * BCAP;

    // act-clear geometry (class range [c0, c1))
    int cc0 = bid * CPB;
    int cc1 = cc0 + hidcnt * 10;
    int cw0 = cc0 >> 5;
    int cnw = (cc1 > cc0) ? ((cc1 - 1) >> 5) - cw0 + 1 : 0;

    float vm0 = 0.f, vm1 = 0.f, acc0 = 0.f, acc1 = 0.f;

    // ---- simulation: 5 regions x 6 steps, 1 gridbar per region, 2 syncs per step ----
    for (int r = 0; r < 5; r++) {
        int u0 = r * 6;
        gridbar(base + 5 + r);
        if (tid < 6) s_rowany[tid] = 0u;
        __syncthreads();
        if (bid < NBACT) {
            // stage act rows u0..u0+5 and per-row any-flags
            for (int i = tid; i < 6*ROWW; i += NTHR) {
                int j = i / ROWW, w = i - j*ROWW;
                uint32_t v = __ldcg(&d_actb[((u0 + j) & (NSLOT-1))*ROWW + w]);
                s_actw[i] = v;
                if (v) s_rowany[j] = 1u;      // benign race
            }
            // clear own class-bits of rows consumed 2 regions ago (atomic: boundary words shared)
            if (tid < 6*cnw) {
                int j = tid / cnw, k = tid - j*cnw;
                int w = cw0 + k;
                int lo = cc0 - w*32; if (lo < 0) lo = 0;
                int hi = cc1 - w*32; if (hi > 32) hi = 32;
                uint32_t mask = ((hi >= 32) ? 0xFFFFFFFFu : ((1u << hi) - 1u))
                                & ~((lo <= 0) ? 0u : ((1u << lo) - 1u));
                int row = (u0 - 12 + j + 2*NSLOT) & (NSLOT-1);
                atomicAnd(&d_actb[row*ROWW + w], ~mask);
            }
        }
        __syncthreads();

        for (int j = 0; j < 6; j++) {
            int u = u0 + j;
            int buf = u & 1;
            const uint32_t* actrow = s_actw + j*ROWW;
            bool rowact = s_rowany[j] != 0u;
            float I0 = 0.f, I1 = 0.f;
            if (rowact && nvalid)
                filter_consume(u, fits ? (lbeg + i0) : i0, fits ? (lbeg + i1) : i1,
                               goff, fits, s_edge, actrow, mybuck, I0, I1);
            if (half == 1 && nvalid) s_part[pair*32 + lane] = make_float2(I0, I1);
            __syncthreads();                              // A
            if (nvalid && half == 0) {
                float2 p = s_part[pair*32 + lane];
                I0 += p.x; I1 += p.y;
                bool hid = n < NHID;
                if (hid && (u % 3) == 2) {
                    float2 ip = *(const float2*)&s_inp[pair*64 + 2*lane];
                    I0 += ip.x; I1 += ip.y;
                }
                vm0 += (I0 - vm0) * 0.1f;
                vm1 += (I1 - vm1) * 0.1f;
                if (!hid) { acc0 += vm0; acc1 += vm1; }
                else {
                    float ve0 = fmaxf(0.f, vm0 - 0.25f);
                    float ve1 = fmaxf(0.f, vm1 - 0.25f);
                    bool f0 = ve0 > 0.f, f1 = ve1 > 0.f;
                    if (f0) vm0 = -0.2f;
                    if (f1) vm1 = -0.2f;
                    *(float2*)&s_vexc[buf*WPB*64 + pair*64 + 2*lane] = make_float2(ve0, ve1);
                    uint32_t b0 = __ballot_sync(0xffffffffu, f0);
                    uint32_t b1 = __ballot_sync(0xffffffffu, f1);
                    uint32_t w0 = spread16(b0 & 0xFFFFu) | (spread16(b1 & 0xFFFFu) << 1);
                    uint32_t w1 = spread16(b0 >> 16)     | (spread16(b1 >> 16) << 1);
                    if (lane == 0) s_fired[buf*WPB*2 + pair*2]     = w0;
                    if (lane == 1) s_fired[buf*WPB*2 + pair*2 + 1] = w1;
                }
            } else if (half == 0) {
                __ballot_sync(0xffffffffu, false);
                __ballot_sync(0xffffffffu, false);
            }
            __syncthreads();                              // B
            if (bid < NBACT)
                launch_phase(u, bid, s_cmeta, s_dl,
                             s_fired + buf*WPB*2, s_vexc + buf*WPB*64);
            // no third sync: launch(u) reads parity buf u&1; neuron(u+1) writes buf (u+1)&1
        }
    }

    if (nvalid && half == 0 && n >= NHID) {
        int o = n - NHID;
        out[(2*lane)   * NOUT + o] = acc0 * (1.0f / (float)TSTEPS);
        out[(2*lane+1) * NOUT + o] = acc1 * (1.0f / (float)TSTEPS);
    }
}

extern "C" void kernel_launch(void* const* d_in, const int* in_sizes, int n_in,
                              void* d_out, int out_size) {
    const float* x   = (const float*)d_in[0];
    const float* W   = (const float*)d_in[1];
    const float* We  = (const float*)d_in[2];
    const float* Le  = (const float*)d_in[3];
    const int*   src = (const int*)d_in[4];
    const int*   tgt = (const int*)d_in[5];
    float* out = (float*)d_out;
    (void)in_sizes; (void)n_in; (void)out_size;

    cudaFuncSetAttribute(sim_kernel, cudaFuncAttributeMaxDynamicSharedMemorySize, SMEM_B);
    dim3 gg(8, 8);
    gemm_kernel<<<gg, 256>>>(x, W);
    sim_kernel<<<NBLK, NTHR, SMEM_B>>>(We, Le, src, tgt, out);
}